// round 8
// baseline (speedup 1.0000x reference)
#include <cuda_runtime.h>

#define BATCH 2
#define LSEQ 2048
#define HDIM 1024
#define NST 16
#define MROWS (BATCH*LSEQ)     // 4096
#define DT_MIN_V 0.001f
#define DT_MAX_V 0.02f
#define NCHUNK 128
#define CHLEN (LSEQ/NCHUNK)    // 16
#define NCH (BATCH*HDIM)       // 2048
#define NGRP 16
#define GCH (NCHUNK/NGRP)      // 8 chunks per group
#define LOG2E 1.4426950408889634f

typedef unsigned long long u64;

// Scratch (__device__ globals: allocation-free rule)
__device__ float2 g_du[BATCH*LSEQ*HDIM];       // (B,L,H) packed {dt, u}
// [chunk][n][s] transposed layouts (coalesced)
__device__ float  g_P  [NCHUNK*NST*NCH];
__device__ float  g_S  [NCHUNK*NST*NCH];
__device__ float  g_Xin[NCHUNK*NST*NCH];
// group-level aggregates [group][n][s]
__device__ float  g_Pg [NGRP*NST*NCH];
__device__ float  g_Sg [NGRP*NST*NCH];
__device__ float  g_Xg [NGRP*NST*NCH];
// Per-channel constant tables, packed pairs, layout [pair i][h]
__device__ u64 g_am2T[8*HDIM];
__device__ u64 g_al2T[8*HDIM];
__device__ u64 g_c2T [8*HDIM];

__device__ __forceinline__ u64 ffma2(u64 a, u64 b, u64 c){
    u64 d;
    asm("fma.rn.f32x2 %0, %1, %2, %3;" : "=l"(d) : "l"(a), "l"(b), "l"(c));
    return d;
}
__device__ __forceinline__ u64 f2u(float x, float y){
    u64 v; asm("mov.b64 %0, {%1, %2};" : "=l"(v) : "f"(x), "f"(y)); return v;
}
__device__ __forceinline__ float2 u2f(u64 v){
    float2 r; asm("mov.b64 {%0, %1}, %2;" : "=f"(r.x), "=f"(r.y) : "l"(v)); return r;
}

// ---------------------------------------------------------------------------
// Precompute per-channel constants (runs once).
// ---------------------------------------------------------------------------
__global__ void precompute_kernel(const float* __restrict__ Alog,
                                  const float* __restrict__ Bp,
                                  const float* __restrict__ Cp){
    const int h = blockIdx.x * blockDim.x + threadIdx.x;
    float am[NST], al2[NST], cs[NST];
    #pragma unroll
    for (int n = 0; n < NST; n++){
        const float A = -expf(Alog[h * NST + n]);
        al2[n] = A * LOG2E;
        am[n]  = exp2f(0.02f * al2[n]);
        cs[n]  = Cp[h * NST + n] * (am[n] - 1.f) * Bp[h * NST + n] / A;
    }
    #pragma unroll
    for (int i = 0; i < 8; i++){
        g_am2T[i * HDIM + h] = f2u(am[2 * i],  am[2 * i + 1]);
        g_al2T[i * HDIM + h] = f2u(al2[2 * i], al2[2 * i + 1]);
        g_c2T [i * HDIM + h] = f2u(cs[2 * i],  cs[2 * i + 1]);
    }
}

// ---------------------------------------------------------------------------
// TF32 tensor-core GEMM, 128x256 block tile, BK=32, 256 threads (8 warps,
// warp tile 64x64). log_dt = U·Wᵀ + b; dt = clamp(exp()); writes g_du={dt,u}.
// ---------------------------------------------------------------------------
__device__ __forceinline__ void cp16(float* s, const float* g){
    unsigned sa = (unsigned)__cvta_generic_to_shared(s);
    asm volatile("cp.async.cg.shared.global [%0], [%1], 16;" :: "r"(sa), "l"(g));
}
__device__ __forceinline__ void ldsm4(unsigned* r, unsigned addr){
    asm volatile("ldmatrix.sync.aligned.m8n8.x4.shared.b16 {%0,%1,%2,%3}, [%4];"
        : "=r"(r[0]), "=r"(r[1]), "=r"(r[2]), "=r"(r[3]) : "r"(addr));
}
__device__ __forceinline__ void mma_tf32(float* d, const unsigned* a,
                                         unsigned b0, unsigned b1){
    asm volatile(
        "mma.sync.aligned.m16n8k8.row.col.f32.tf32.tf32.f32 "
        "{%0,%1,%2,%3}, {%4,%5,%6,%7}, {%8,%9}, {%0,%1,%2,%3};"
        : "+f"(d[0]), "+f"(d[1]), "+f"(d[2]), "+f"(d[3])
        : "r"(a[0]), "r"(a[1]), "r"(a[2]), "r"(a[3]), "r"(b0), "r"(b1));
}

#define GEMM_SMEM_STG 12288      // floats per stage: (128+256)*32
#define GEMM_B_OFF    4096       // floats: A tile is 128*32

__global__ __launch_bounds__(256, 1) void gemm_tf32_kernel(
        const float* __restrict__ U, const float* __restrict__ W,
        const float* __restrict__ bias){
    extern __shared__ float smem[];
    const int tid  = threadIdx.x;
    const int lane = tid & 31;
    const int wid  = tid >> 5;
    const int wm   = wid & 1;             // 2 warps along M (64 each)
    const int wn   = wid >> 1;            // 4 warps along N (64 each)
    const int bm   = blockIdx.y * 128;
    const int bn   = blockIdx.x * 256;

    float acc[4][8][4];
    #pragma unroll
    for (int i = 0; i < 4; i++)
        #pragma unroll
        for (int j = 0; j < 8; j++)
            #pragma unroll
            for (int r = 0; r < 4; r++) acc[i][j][r] = 0.f;

    const int lrow = tid >> 3;            // 0..31
    const int lkc  = tid & 7;             // 16B chunk in row

    unsigned smemBase = (unsigned)__cvta_generic_to_shared(smem);
    const unsigned aRowOff = (unsigned)((wm * 64 + (lane & 15)) * 128);
    const unsigned bRowOff = (unsigned)((wn * 64 + ((lane & 16) >> 1) + (lane & 7)) * 128);
    int physA[4], physB[4];
    #pragma unroll
    for (int ks = 0; ks < 4; ks++){
        physA[ks] = ((2 * ks + (lane >> 4)) ^ (lane & 7)) * 16;
        physB[ks] = ((2 * ks + ((lane >> 3) & 1)) ^ (lane & 7)) * 16;
    }

    #define LOAD_TILE(KT, STG) do {                                            \
        float* A_s = smem + (STG) * GEMM_SMEM_STG;                             \
        float* B_s = A_s + GEMM_B_OFF;                                         \
        _Pragma("unroll")                                                      \
        for (int i = 0; i < 4; i++){                                           \
            int row  = lrow + i * 32;                                          \
            int phys = lkc ^ (row & 7);                                        \
            cp16(A_s + row * 32 + phys * 4,                                    \
                 U + (size_t)(bm + row) * 1024 + (KT) * 32 + lkc * 4);         \
        }                                                                      \
        _Pragma("unroll")                                                      \
        for (int i = 0; i < 8; i++){                                           \
            int row  = lrow + i * 32;                                          \
            int phys = lkc ^ (row & 7);                                        \
            cp16(B_s + row * 32 + phys * 4,                                    \
                 W + (size_t)(bn + row) * 1024 + (KT) * 32 + lkc * 4);         \
        }                                                                      \
        asm volatile("cp.async.commit_group;");                                \
    } while (0)

    LOAD_TILE(0, 0);

    for (int kt = 0; kt < 32; kt++){
        const int cur = kt & 1;
        if (kt < 31) LOAD_TILE(kt + 1, cur ^ 1);
        if (kt < 31) asm volatile("cp.async.wait_group 1;");
        else         asm volatile("cp.async.wait_group 0;");
        __syncthreads();

        unsigned aB = smemBase + cur * (GEMM_SMEM_STG * 4) + aRowOff;
        unsigned bB = smemBase + cur * (GEMM_SMEM_STG * 4) + GEMM_B_OFF * 4 + bRowOff;
        #pragma unroll
        for (int ks = 0; ks < 4; ks++){
            unsigned a[4][4], bb[4][4];
            #pragma unroll
            for (int mt = 0; mt < 4; mt++)
                ldsm4(a[mt], aB + mt * 16 * 128 + physA[ks]);
            #pragma unroll
            for (int tp = 0; tp < 4; tp++)
                ldsm4(bb[tp], bB + tp * 16 * 128 + physB[ks]);
            #pragma unroll
            for (int mt = 0; mt < 4; mt++)
                #pragma unroll
                for (int nt = 0; nt < 8; nt++)
                    mma_tf32(acc[mt][nt], a[mt],
                             bb[nt >> 1][(nt & 1) * 2], bb[nt >> 1][(nt & 1) * 2 + 1]);
        }
        __syncthreads();
    }

    const int rbase = bm + wm * 64 + (lane >> 2);
    const int gbase = bn + wn * 64 + 2 * (lane & 3);
    float bv[8][2];
    #pragma unroll
    for (int nt = 0; nt < 8; nt++){
        bv[nt][0] = __ldg(bias + gbase + nt * 8);
        bv[nt][1] = __ldg(bias + gbase + nt * 8 + 1);
    }
    #pragma unroll
    for (int mt = 0; mt < 4; mt++)
        #pragma unroll
        for (int nt = 0; nt < 8; nt++)
            #pragma unroll
            for (int rr = 0; rr < 2; rr++){
                const int m = rbase + mt * 16 + rr * 8;
                const int g0 = gbase + nt * 8;
                float v0 = acc[mt][nt][rr * 2]     + bv[nt][0];
                float v1 = acc[mt][nt][rr * 2 + 1] + bv[nt][1];
                v0 = fminf(fmaxf(__expf(v0), DT_MIN_V), DT_MAX_V);
                v1 = fminf(fmaxf(__expf(v1), DT_MIN_V), DT_MAX_V);
                const float2 uv = *(const float2*)&U[(size_t)m * HDIM + g0];
                float4 w;
                w.x = v0; w.y = uv.x;
                w.z = v1; w.w = uv.y;
                *(float4*)&g_du[(size_t)m * HDIM + g0] = w;
            }
}

// ---------------------------------------------------------------------------
// Step macros (register-only, fully inline).
// ---------------------------------------------------------------------------
#define FAST_STEP(uu) do {                                                     \
    const u64 _u2 = f2u((uu), (uu));                                           \
    _Pragma("unroll")                                                          \
    for (int _i = 0; _i < 8; _i++) x2[_i] = ffma2(x2[_i], am2[_i], _u2);       \
} while (0)

#define SLOW_STEP(dtv, uv) do {                                                \
    _Pragma("unroll")                                                          \
    for (int _i = 0; _i < 8; _i++){                                            \
        float2 _xv = u2f(x2[_i]);                                              \
        const float2 _av = u2f(am2[_i]);                                       \
        const float2 _lv = u2f(al2[_i]);                                       \
        {                                                                      \
            const float _ab = exp2f((dtv) * _lv.x);                            \
            _xv.x = fmaf(_xv.x, _ab, (_ab - 1.f) / (_av.x - 1.f) * (uv));      \
        }                                                                      \
        {                                                                      \
            const float _ab = exp2f((dtv) * _lv.y);                            \
            _xv.y = fmaf(_xv.y, _ab, (_ab - 1.f) / (_av.y - 1.f) * (uv));      \
        }                                                                      \
        x2[_i] = f2u(_xv.x, _xv.y);                                            \
    }                                                                          \
} while (0)

// ---------------------------------------------------------------------------
// Pass 1: per-(channel,chunk) reduce → P, S  (layouts [chunk][n][s])
// ---------------------------------------------------------------------------
__global__ __launch_bounds__(128) void scan_reduce_kernel(){
    const int tid = threadIdx.x;
    const int s = blockIdx.x * 128 + tid;
    const int chunk = blockIdx.y;
    const int b = s >> 10;
    const int h = s & 1023;

    const size_t base = ((size_t)(b * LSEQ + chunk * CHLEN)) * HDIM + h;
    float2 d[CHLEN];
    #pragma unroll
    for (int j = 0; j < CHLEN; j++)
        d[j] = __ldg((const float2*)&g_du[base + (size_t)j * HDIM]);

    u64 am2[8], al2[8], x2[8];
    #pragma unroll
    for (int i = 0; i < 8; i++){
        am2[i] = g_am2T[i * HDIM + h];
        al2[i] = g_al2T[i * HDIM + h];
        x2[i] = 0ull;
    }

    float dtsum = 0.f;
    bool fast = true;
    #pragma unroll
    for (int j = 0; j < CHLEN; j++){ fast &= (d[j].x == DT_MAX_V); dtsum += d[j].x; }

    if (fast){
        #pragma unroll
        for (int j = 0; j < CHLEN; j++) FAST_STEP(d[j].y);
    } else {
        #pragma unroll
        for (int j = 0; j < CHLEN; j++){
            if (d[j].x == DT_MAX_V) FAST_STEP(d[j].y);
            else                    SLOW_STEP(d[j].x, d[j].y);
        }
    }

    float* Pp = g_P + (size_t)chunk * NST * NCH + s;
    float* Sp = g_S + (size_t)chunk * NST * NCH + s;
    #pragma unroll
    for (int i = 0; i < 8; i++){
        const float2 lv = u2f(al2[i]);
        const float2 xv = u2f(x2[i]);
        Pp[(size_t)(2 * i)     * NCH] = exp2f(lv.x * dtsum);
        Pp[(size_t)(2 * i + 1) * NCH] = exp2f(lv.y * dtsum);
        Sp[(size_t)(2 * i)     * NCH] = xv.x;
        Sp[(size_t)(2 * i + 1) * NCH] = xv.y;
    }
}

// ---------------------------------------------------------------------------
// Stitch, 3-phase parallel scan over 128 chunks (16 groups x 8).
// stride = NST*NCH/4 float4 per chunk (= 8192).
// ---------------------------------------------------------------------------
#define STRIDE4 (NST*NCH/4)

// Phase 1: fold each group of 8 chunks into aggregate (Pg, Sg).
__global__ void scan_stitch1_kernel(){
    const int id = blockIdx.x * blockDim.x + threadIdx.x;  // 0..8191
    const int g  = blockIdx.y;
    const float4* P4 = (const float4*)g_P;
    const float4* S4 = (const float4*)g_S;
    float4 Pc[GCH], Sc[GCH];
    #pragma unroll
    for (int c = 0; c < GCH; c++){
        Pc[c] = P4[(size_t)(g * GCH + c) * STRIDE4 + id];
        Sc[c] = S4[(size_t)(g * GCH + c) * STRIDE4 + id];
    }
    float4 p = Pc[0], s = Sc[0];
    #pragma unroll
    for (int c = 1; c < GCH; c++){
        s.x = fmaf(Pc[c].x, s.x, Sc[c].x);
        s.y = fmaf(Pc[c].y, s.y, Sc[c].y);
        s.z = fmaf(Pc[c].z, s.z, Sc[c].z);
        s.w = fmaf(Pc[c].w, s.w, Sc[c].w);
        p.x *= Pc[c].x; p.y *= Pc[c].y; p.z *= Pc[c].z; p.w *= Pc[c].w;
    }
    ((float4*)g_Pg)[(size_t)g * STRIDE4 + id] = p;
    ((float4*)g_Sg)[(size_t)g * STRIDE4 + id] = s;
}

// Phase 2: serial fold of 16 group aggregates -> group-start states Xg.
__global__ void scan_stitch2_kernel(){
    const int id = blockIdx.x * blockDim.x + threadIdx.x;  // 0..8191
    const float4* Pg4 = (const float4*)g_Pg;
    const float4* Sg4 = (const float4*)g_Sg;
    float4* Xg4 = (float4*)g_Xg;
    float4 Pg[NGRP], Sg[NGRP];
    #pragma unroll
    for (int g = 0; g < NGRP; g++){
        Pg[g] = Pg4[(size_t)g * STRIDE4 + id];
        Sg[g] = Sg4[(size_t)g * STRIDE4 + id];
    }
    float4 x = make_float4(0.f, 0.f, 0.f, 0.f);
    #pragma unroll
    for (int g = 0; g < NGRP; g++){
        Xg4[(size_t)g * STRIDE4 + id] = x;
        x.x = fmaf(Pg[g].x, x.x, Sg[g].x);
        x.y = fmaf(Pg[g].y, x.y, Sg[g].y);
        x.z = fmaf(Pg[g].z, x.z, Sg[g].z);
        x.w = fmaf(Pg[g].w, x.w, Sg[g].w);
    }
}

// Phase 3: expand group-start states into per-chunk Xin.
__global__ void scan_stitch3_kernel(){
    const int id = blockIdx.x * blockDim.x + threadIdx.x;  // 0..8191
    const int g  = blockIdx.y;
    const float4* P4 = (const float4*)g_P;
    const float4* S4 = (const float4*)g_S;
    float4* X4 = (float4*)g_Xin;
    float4 Pc[GCH], Sc[GCH];
    #pragma unroll
    for (int c = 0; c < GCH; c++){
        Pc[c] = P4[(size_t)(g * GCH + c) * STRIDE4 + id];
        Sc[c] = S4[(size_t)(g * GCH + c) * STRIDE4 + id];
    }
    float4 x = ((const float4*)g_Xg)[(size_t)g * STRIDE4 + id];
    #pragma unroll
    for (int c = 0; c < GCH; c++){
        X4[(size_t)(g * GCH + c) * STRIDE4 + id] = x;
        x.x = fmaf(Pc[c].x, x.x, Sc[c].x);
        x.y = fmaf(Pc[c].y, x.y, Sc[c].y);
        x.z = fmaf(Pc[c].z, x.z, Sc[c].z);
        x.w = fmaf(Pc[c].w, x.w, Sc[c].w);
    }
}

// ---------------------------------------------------------------------------
// Pass 3: final scan + output.
// ---------------------------------------------------------------------------
__global__ __launch_bounds__(128) void scan_final_kernel(
        const float* __restrict__ Dp, float* __restrict__ out){
    const int tid = threadIdx.x;
    const int s = blockIdx.x * 128 + tid;
    const int chunk = blockIdx.y;
    const int b = s >> 10;
    const int h = s & 1023;

    const size_t base = ((size_t)(b * LSEQ + chunk * CHLEN)) * HDIM + h;
    float2 d[CHLEN];
    #pragma unroll
    for (int j = 0; j < CHLEN; j++)
        d[j] = __ldg((const float2*)&g_du[base + (size_t)j * HDIM]);

    u64 am2[8], c2[8], x2[8];
    #pragma unroll
    for (int i = 0; i < 8; i++){
        am2[i] = g_am2T[i * HDIM + h];
        c2[i]  = g_c2T [i * HDIM + h];
    }
    const float Dh = __ldg(Dp + h);

    {
        const float* Xp = g_Xin + (size_t)chunk * NST * NCH + s;
        #pragma unroll
        for (int i = 0; i < 8; i++)
            x2[i] = f2u(Xp[(size_t)(2 * i) * NCH], Xp[(size_t)(2 * i + 1) * NCH]);
    }

    float* op = out + base;

    bool fast = true;
    #pragma unroll
    for (int j = 0; j < CHLEN; j++) fast &= (d[j].x == DT_MAX_V);

    #define Y_EMIT(j, uv) do {                                                 \
        u64 ya = 0ull, yb = 0ull;                                              \
        _Pragma("unroll")                                                      \
        for (int _i = 0; _i < 4; _i++) ya = ffma2(c2[_i], x2[_i], ya);         \
        _Pragma("unroll")                                                      \
        for (int _i = 4; _i < 8; _i++) yb = ffma2(c2[_i], x2[_i], yb);         \
        const float2 _va = u2f(ya);                                            \
        const float2 _vb = u2f(yb);                                            \
        op[(size_t)(j) * HDIM] = fmaf(Dh, (uv), (_va.x + _va.y) + (_vb.x + _vb.y)); \
    } while (0)

    if (fast){
        #pragma unroll
        for (int j = 0; j < CHLEN; j++){
            FAST_STEP(d[j].y);
            Y_EMIT(j, d[j].y);
        }
    } else {
        u64 al2[8];
        #pragma unroll
        for (int i = 0; i < 8; i++) al2[i] = g_al2T[i * HDIM + h];
        #pragma unroll
        for (int j = 0; j < CHLEN; j++){
            if (d[j].x == DT_MAX_V) FAST_STEP(d[j].y);
            else                    SLOW_STEP(d[j].x, d[j].y);
            Y_EMIT(j, d[j].y);
        }
    }
    #undef Y_EMIT
}

// ---------------------------------------------------------------------------
extern "C" void kernel_launch(void* const* d_in, const int* in_sizes, int n_in,
                              void* d_out, int out_size){
    const float* u    = (const float*)d_in[0];
    const float* Alog = (const float*)d_in[1];
    const float* Bp   = (const float*)d_in[2];
    const float* Cp   = (const float*)d_in[3];
    const float* Dp   = (const float*)d_in[4];
    const float* Wdt  = (const float*)d_in[5];
    const float* bdt  = (const float*)d_in[6];
    float* out = (float*)d_out;

    cudaFuncSetAttribute(gemm_tf32_kernel,
                         cudaFuncAttributeMaxDynamicSharedMemorySize, 98304);

    precompute_kernel<<<HDIM / 128, 128>>>(Alog, Bp, Cp);

    dim3 ggrid(HDIM / 256, MROWS / 128);            // (4, 32)
    gemm_tf32_kernel<<<ggrid, 256, 98304>>>(u, Wdt, bdt);

    scan_reduce_kernel<<<dim3(NCH / 128, NCHUNK), 128>>>();
    scan_stitch1_kernel<<<dim3(STRIDE4 / 256, NGRP), 256>>>();
    scan_stitch2_kernel<<<STRIDE4 / 256, 256>>>();
    scan_stitch3_kernel<<<dim3(STRIDE4 / 256, NGRP), 256>>>();
    scan_final_kernel<<<dim3(NCH / 128, NCHUNK), 128>>>(Dp, out);
}

// round 9
// speedup vs baseline: 1.1462x; 1.1462x over previous
#include <cuda_runtime.h>

#define BATCH 2
#define LSEQ 2048
#define HDIM 1024
#define NST 16
#define MROWS (BATCH*LSEQ)     // 4096
#define DT_MIN_V 0.001f
#define DT_MAX_V 0.02f
#define NGRP 16
#define GLEN (LSEQ/NGRP)       // 128 steps per group
#define NB (GLEN/16)           // 8 batches of 16
#define NCH (BATCH*HDIM)       // 2048
#define LOG2E 1.4426950408889634f

typedef unsigned long long u64;

// Scratch (__device__ globals: allocation-free rule)
__device__ float2 g_du[BATCH*LSEQ*HDIM];       // (B,L,H) packed {dt, u}
// group-level aggregates / start states, layout [group][n][s]
__device__ float  g_Pg [NGRP*NST*NCH];
__device__ float  g_Sg [NGRP*NST*NCH];
__device__ float  g_Xg [NGRP*NST*NCH];
// Per-channel constant tables, packed pairs, layout [pair i][h]
__device__ u64 g_am2T[8*HDIM];
__device__ u64 g_al2T[8*HDIM];
__device__ u64 g_c2T [8*HDIM];

__device__ __forceinline__ u64 ffma2(u64 a, u64 b, u64 c){
    u64 d;
    asm("fma.rn.f32x2 %0, %1, %2, %3;" : "=l"(d) : "l"(a), "l"(b), "l"(c));
    return d;
}
__device__ __forceinline__ u64 f2u(float x, float y){
    u64 v; asm("mov.b64 %0, {%1, %2};" : "=l"(v) : "f"(x), "f"(y)); return v;
}
__device__ __forceinline__ float2 u2f(u64 v){
    float2 r; asm("mov.b64 {%0, %1}, %2;" : "=f"(r.x), "=f"(r.y) : "l"(v)); return r;
}

// ---------------------------------------------------------------------------
// Precompute per-channel constants (runs once).
// ---------------------------------------------------------------------------
__global__ void precompute_kernel(const float* __restrict__ Alog,
                                  const float* __restrict__ Bp,
                                  const float* __restrict__ Cp){
    const int h = blockIdx.x * blockDim.x + threadIdx.x;
    float am[NST], al2[NST], cs[NST];
    #pragma unroll
    for (int n = 0; n < NST; n++){
        const float A = -expf(Alog[h * NST + n]);
        al2[n] = A * LOG2E;
        am[n]  = exp2f(0.02f * al2[n]);
        cs[n]  = Cp[h * NST + n] * (am[n] - 1.f) * Bp[h * NST + n] / A;
    }
    #pragma unroll
    for (int i = 0; i < 8; i++){
        g_am2T[i * HDIM + h] = f2u(am[2 * i],  am[2 * i + 1]);
        g_al2T[i * HDIM + h] = f2u(al2[2 * i], al2[2 * i + 1]);
        g_c2T [i * HDIM + h] = f2u(cs[2 * i],  cs[2 * i + 1]);
    }
}

// ---------------------------------------------------------------------------
// TF32 tensor-core GEMM — exact R7 (best-run) configuration: 128x128 tile,
// BK=32, 256 threads. log_dt = U·Wᵀ + b; dt = clamp(exp()); writes g_du.
// ---------------------------------------------------------------------------
__device__ __forceinline__ void cp16(float* s, const float* g){
    unsigned sa = (unsigned)__cvta_generic_to_shared(s);
    asm volatile("cp.async.cg.shared.global [%0], [%1], 16;" :: "r"(sa), "l"(g));
}
__device__ __forceinline__ void ldsm4(unsigned* r, unsigned addr){
    asm volatile("ldmatrix.sync.aligned.m8n8.x4.shared.b16 {%0,%1,%2,%3}, [%4];"
        : "=r"(r[0]), "=r"(r[1]), "=r"(r[2]), "=r"(r[3]) : "r"(addr));
}
__device__ __forceinline__ void mma_tf32(float* d, const unsigned* a,
                                         unsigned b0, unsigned b1){
    asm volatile(
        "mma.sync.aligned.m16n8k8.row.col.f32.tf32.tf32.f32 "
        "{%0,%1,%2,%3}, {%4,%5,%6,%7}, {%8,%9}, {%0,%1,%2,%3};"
        : "+f"(d[0]), "+f"(d[1]), "+f"(d[2]), "+f"(d[3])
        : "r"(a[0]), "r"(a[1]), "r"(a[2]), "r"(a[3]), "r"(b0), "r"(b1));
}

__global__ __launch_bounds__(256) void gemm_tf32_kernel(
        const float* __restrict__ U, const float* __restrict__ W,
        const float* __restrict__ bias){
    extern __shared__ float smem[];
    const int tid  = threadIdx.x;
    const int lane = tid & 31;
    const int wid  = tid >> 5;
    const int wm   = wid & 1;
    const int wn   = wid >> 1;
    const int bm   = blockIdx.y * 128;
    const int bn   = blockIdx.x * 128;

    float acc[4][4][4];
    #pragma unroll
    for (int i = 0; i < 4; i++)
        #pragma unroll
        for (int j = 0; j < 4; j++)
            #pragma unroll
            for (int r = 0; r < 4; r++) acc[i][j][r] = 0.f;

    const int lrow = tid >> 3;
    const int lkc  = tid & 7;

    unsigned smemBase = (unsigned)__cvta_generic_to_shared(smem);
    const unsigned aRowOff = (unsigned)((wm * 64 + (lane & 15)) * 128);
    const unsigned bRowOff = (unsigned)((wn * 32 + ((lane & 16) >> 1) + (lane & 7)) * 128);
    int physA[4], physB[4];
    #pragma unroll
    for (int ks = 0; ks < 4; ks++){
        physA[ks] = ((2 * ks + (lane >> 4)) ^ (lane & 7)) * 16;
        physB[ks] = ((2 * ks + ((lane >> 3) & 1)) ^ (lane & 7)) * 16;
    }

    #define LOAD_TILE(KT, STG) do {                                            \
        float* A_s = smem + (STG) * 8192;                                      \
        float* B_s = A_s + 4096;                                               \
        _Pragma("unroll")                                                      \
        for (int i = 0; i < 4; i++){                                           \
            int row  = lrow + i * 32;                                          \
            int phys = lkc ^ (row & 7);                                        \
            cp16(A_s + row * 32 + phys * 4,                                    \
                 U + (size_t)(bm + row) * 1024 + (KT) * 32 + lkc * 4);         \
            cp16(B_s + row * 32 + phys * 4,                                    \
                 W + (size_t)(bn + row) * 1024 + (KT) * 32 + lkc * 4);         \
        }                                                                      \
        asm volatile("cp.async.commit_group;");                                \
    } while (0)

    LOAD_TILE(0, 0);

    for (int kt = 0; kt < 32; kt++){
        const int cur = kt & 1;
        if (kt < 31) LOAD_TILE(kt + 1, cur ^ 1);
        if (kt < 31) asm volatile("cp.async.wait_group 1;");
        else         asm volatile("cp.async.wait_group 0;");
        __syncthreads();

        unsigned aB = smemBase + cur * 32768 + aRowOff;
        unsigned bB = smemBase + cur * 32768 + 16384 + bRowOff;
        #pragma unroll
        for (int ks = 0; ks < 4; ks++){
            unsigned a[4][4], bb[2][4];
            #pragma unroll
            for (int mt = 0; mt < 4; mt++)
                ldsm4(a[mt], aB + mt * 16 * 128 + physA[ks]);
            #pragma unroll
            for (int tp = 0; tp < 2; tp++)
                ldsm4(bb[tp], bB + tp * 16 * 128 + physB[ks]);
            #pragma unroll
            for (int mt = 0; mt < 4; mt++)
                #pragma unroll
                for (int nt = 0; nt < 4; nt++)
                    mma_tf32(acc[mt][nt], a[mt],
                             bb[nt >> 1][(nt & 1) * 2], bb[nt >> 1][(nt & 1) * 2 + 1]);
        }
        __syncthreads();
    }

    const int rbase = bm + wm * 64 + (lane >> 2);
    const int gbase = bn + wn * 32 + 2 * (lane & 3);
    float bv[4][2];
    #pragma unroll
    for (int nt = 0; nt < 4; nt++){
        bv[nt][0] = __ldg(bias + gbase + nt * 8);
        bv[nt][1] = __ldg(bias + gbase + nt * 8 + 1);
    }
    #pragma unroll
    for (int mt = 0; mt < 4; mt++)
        #pragma unroll
        for (int nt = 0; nt < 4; nt++)
            #pragma unroll
            for (int rr = 0; rr < 2; rr++){
                const int m = rbase + mt * 16 + rr * 8;
                const int g0 = gbase + nt * 8;
                float v0 = acc[mt][nt][rr * 2]     + bv[nt][0];
                float v1 = acc[mt][nt][rr * 2 + 1] + bv[nt][1];
                v0 = fminf(fmaxf(__expf(v0), DT_MIN_V), DT_MAX_V);
                v1 = fminf(fmaxf(__expf(v1), DT_MIN_V), DT_MAX_V);
                const float2 uv = *(const float2*)&U[(size_t)m * HDIM + g0];
                float4 w;
                w.x = v0; w.y = uv.x;
                w.z = v1; w.w = uv.y;
                *(float4*)&g_du[(size_t)m * HDIM + g0] = w;
            }
}

// ---------------------------------------------------------------------------
// Step macros (register-only, fully inline).
// ---------------------------------------------------------------------------
#define FAST_STEP(uu) do {                                                     \
    const u64 _u2 = f2u((uu), (uu));                                           \
    _Pragma("unroll")                                                          \
    for (int _i = 0; _i < 8; _i++) x2[_i] = ffma2(x2[_i], am2[_i], _u2);       \
} while (0)

#define SLOW_STEP(dtv, uv) do {                                                \
    _Pragma("unroll")                                                          \
    for (int _i = 0; _i < 8; _i++){                                            \
        float2 _xv = u2f(x2[_i]);                                              \
        const float2 _av = u2f(am2[_i]);                                       \
        const float2 _lv = u2f(al2[_i]);                                       \
        {                                                                      \
            const float _ab = exp2f((dtv) * _lv.x);                            \
            _xv.x = fmaf(_xv.x, _ab, (_ab - 1.f) / (_av.x - 1.f) * (uv));      \
        }                                                                      \
        {                                                                      \
            const float _ab = exp2f((dtv) * _lv.y);                            \
            _xv.y = fmaf(_xv.y, _ab, (_ab - 1.f) / (_av.y - 1.f) * (uv));      \
        }                                                                      \
        x2[_i] = f2u(_xv.x, _xv.y);                                            \
    }                                                                          \
} while (0)

// ---------------------------------------------------------------------------
// Pass 1: per-(channel, group) reduce over 128 steps -> group aggregates
// (Pg, Sg). 8 batches of 16 preloaded LDG.64 each.
// ---------------------------------------------------------------------------
__global__ __launch_bounds__(128) void scan_reduce_kernel(){
    const int tid = threadIdx.x;
    const int s = blockIdx.x * 128 + tid;      // channel
    const int g = blockIdx.y;                  // group
    const int b = s >> 10;
    const int h = s & 1023;

    u64 am2[8], al2[8], x2[8];
    #pragma unroll
    for (int i = 0; i < 8; i++){
        am2[i] = g_am2T[i * HDIM + h];
        al2[i] = g_al2T[i * HDIM + h];
        x2[i] = 0ull;
    }

    const size_t base = ((size_t)(b * LSEQ + g * GLEN)) * HDIM + h;
    float dtsum = 0.f;

    #pragma unroll 1
    for (int bt = 0; bt < NB; bt++){
        float2 d[16];
        #pragma unroll
        for (int j = 0; j < 16; j++)
            d[j] = __ldg((const float2*)&g_du[base + (size_t)(bt * 16 + j) * HDIM]);
        bool fast = true;
        #pragma unroll
        for (int j = 0; j < 16; j++){ fast &= (d[j].x == DT_MAX_V); dtsum += d[j].x; }
        if (fast){
            #pragma unroll
            for (int j = 0; j < 16; j++) FAST_STEP(d[j].y);
        } else {
            #pragma unroll
            for (int j = 0; j < 16; j++){
                if (d[j].x == DT_MAX_V) FAST_STEP(d[j].y);
                else                    SLOW_STEP(d[j].x, d[j].y);
            }
        }
    }

    float* Pp = g_Pg + (size_t)g * NST * NCH + s;
    float* Sp = g_Sg + (size_t)g * NST * NCH + s;
    #pragma unroll
    for (int i = 0; i < 8; i++){
        const float2 lv = u2f(al2[i]);
        const float2 xv = u2f(x2[i]);
        Pp[(size_t)(2 * i)     * NCH] = exp2f(lv.x * dtsum);
        Pp[(size_t)(2 * i + 1) * NCH] = exp2f(lv.y * dtsum);
        Sp[(size_t)(2 * i)     * NCH] = xv.x;
        Sp[(size_t)(2 * i + 1) * NCH] = xv.y;
    }
}

// ---------------------------------------------------------------------------
// Pass 2: fold 16 group aggregates -> group start states Xg. One exposure.
// ---------------------------------------------------------------------------
#define STRIDE4 (NST*NCH/4)
__global__ void scan_stitch_kernel(){
    const int id = blockIdx.x * blockDim.x + threadIdx.x;  // 0..8191
    const float4* Pg4 = (const float4*)g_Pg;
    const float4* Sg4 = (const float4*)g_Sg;
    float4* Xg4 = (float4*)g_Xg;
    float4 Pg[NGRP], Sg[NGRP];
    #pragma unroll
    for (int g = 0; g < NGRP; g++){
        Pg[g] = Pg4[(size_t)g * STRIDE4 + id];
        Sg[g] = Sg4[(size_t)g * STRIDE4 + id];
    }
    float4 x = make_float4(0.f, 0.f, 0.f, 0.f);
    #pragma unroll
    for (int g = 0; g < NGRP; g++){
        Xg4[(size_t)g * STRIDE4 + id] = x;
        x.x = fmaf(Pg[g].x, x.x, Sg[g].x);
        x.y = fmaf(Pg[g].y, x.y, Sg[g].y);
        x.z = fmaf(Pg[g].z, x.z, Sg[g].z);
        x.w = fmaf(Pg[g].w, x.w, Sg[g].w);
    }
}

// ---------------------------------------------------------------------------
// Pass 3: final scan + output. Thread = (channel, group); starts from Xg,
// replays 128 steps emitting y each step.
// ---------------------------------------------------------------------------
__global__ __launch_bounds__(128) void scan_final_kernel(
        const float* __restrict__ Dp, float* __restrict__ out){
    const int tid = threadIdx.x;
    const int s = blockIdx.x * 128 + tid;
    const int g = blockIdx.y;
    const int b = s >> 10;
    const int h = s & 1023;

    u64 am2[8], c2[8], x2[8];
    #pragma unroll
    for (int i = 0; i < 8; i++){
        am2[i] = g_am2T[i * HDIM + h];
        c2[i]  = g_c2T [i * HDIM + h];
    }
    const float Dh = __ldg(Dp + h);

    {   // group start state (coalesced: [group][n][s])
        const float* Xp = g_Xg + (size_t)g * NST * NCH + s;
        #pragma unroll
        for (int i = 0; i < 8; i++)
            x2[i] = f2u(Xp[(size_t)(2 * i) * NCH], Xp[(size_t)(2 * i + 1) * NCH]);
    }

    const size_t base = ((size_t)(b * LSEQ + g * GLEN)) * HDIM + h;
    float* op = out + base;

    #define Y_EMIT(j, uv) do {                                                 \
        u64 ya = 0ull, yb = 0ull;                                              \
        _Pragma("unroll")                                                      \
        for (int _i = 0; _i < 4; _i++) ya = ffma2(c2[_i], x2[_i], ya);         \
        _Pragma("unroll")                                                      \
        for (int _i = 4; _i < 8; _i++) yb = ffma2(c2[_i], x2[_i], yb);         \
        const float2 _va = u2f(ya);                                            \
        const float2 _vb = u2f(yb);                                            \
        op[(size_t)(j) * HDIM] = fmaf(Dh, (uv), (_va.x + _va.y) + (_vb.x + _vb.y)); \
    } while (0)

    #pragma unroll 1
    for (int bt = 0; bt < NB; bt++){
        float2 d[16];
        #pragma unroll
        for (int j = 0; j < 16; j++)
            d[j] = __ldg((const float2*)&g_du[base + (size_t)(bt * 16 + j) * HDIM]);
        bool fast = true;
        #pragma unroll
        for (int j = 0; j < 16; j++) fast &= (d[j].x == DT_MAX_V);
        if (fast){
            #pragma unroll
            for (int j = 0; j < 16; j++){
                FAST_STEP(d[j].y);
                Y_EMIT(bt * 16 + j, d[j].y);
            }
        } else {
            u64 al2[8];
            #pragma unroll
            for (int i = 0; i < 8; i++) al2[i] = g_al2T[i * HDIM + h];
            #pragma unroll
            for (int j = 0; j < 16; j++){
                if (d[j].x == DT_MAX_V) FAST_STEP(d[j].y);
                else                    SLOW_STEP(d[j].x, d[j].y);
                Y_EMIT(bt * 16 + j, d[j].y);
            }
        }
    }
    #undef Y_EMIT
}

// ---------------------------------------------------------------------------
extern "C" void kernel_launch(void* const* d_in, const int* in_sizes, int n_in,
                              void* d_out, int out_size){
    const float* u    = (const float*)d_in[0];
    const float* Alog = (const float*)d_in[1];
    const float* Bp   = (const float*)d_in[2];
    const float* Cp   = (const float*)d_in[3];
    const float* Dp   = (const float*)d_in[4];
    const float* Wdt  = (const float*)d_in[5];
    const float* bdt  = (const float*)d_in[6];
    float* out = (float*)d_out;

    cudaFuncSetAttribute(gemm_tf32_kernel,
                         cudaFuncAttributeMaxDynamicSharedMemorySize, 65536);

    precompute_kernel<<<HDIM / 128, 128>>>(Alog, Bp, Cp);

    dim3 ggrid(HDIM / 128, MROWS / 128);            // (8, 32)
    gemm_tf32_kernel<<<ggrid, 256, 65536>>>(u, Wdt, bdt);

    scan_reduce_kernel<<<dim3(NCH / 128, NGRP), 128>>>();
    scan_stitch_kernel<<<STRIDE4 / 256, 256>>>();
    scan_final_kernel<<<dim3(NCH / 128, NGRP), 128>>>(Dp, out);
}

// round 10
// speedup vs baseline: 1.3850x; 1.2083x over previous
#include <cuda_runtime.h>
#include <cuda_bf16.h>

#define BATCH 2
#define LSEQ 2048
#define HDIM 1024
#define NST 16
#define MROWS (BATCH*LSEQ)     // 4096
#define DT_MIN_V 0.001f
#define DT_MAX_V 0.02f
#define NGRP 16
#define GLEN (LSEQ/NGRP)       // 128 steps per group
#define NB (GLEN/16)           // 8 batches of 16
#define NCH (BATCH*HDIM)       // 2048
#define LOG2E 1.4426950408889634f

typedef unsigned long long u64;

// Scratch (__device__ globals: allocation-free rule)
__device__ float2 g_du[BATCH*LSEQ*HDIM];       // (B,L,H) packed {dt, u}
__device__ __nv_bfloat16 g_Ub[MROWS*HDIM];     // bf16 copy of u (GEMM A)
__device__ __nv_bfloat16 g_Wb[HDIM*HDIM];      // bf16 copy of W_dt (GEMM B)
// group-level aggregates / start states, layout [group][n][s]
__device__ float  g_Pg [NGRP*NST*NCH];
__device__ float  g_Sg [NGRP*NST*NCH];
__device__ float  g_Xg [NGRP*NST*NCH];
// Per-channel constant tables, packed pairs, layout [pair i][h]
__device__ u64 g_am2T[8*HDIM];
__device__ u64 g_al2T[8*HDIM];
__device__ u64 g_c2T [8*HDIM];

__device__ __forceinline__ u64 ffma2(u64 a, u64 b, u64 c){
    u64 d;
    asm("fma.rn.f32x2 %0, %1, %2, %3;" : "=l"(d) : "l"(a), "l"(b), "l"(c));
    return d;
}
__device__ __forceinline__ u64 f2u(float x, float y){
    u64 v; asm("mov.b64 %0, {%1, %2};" : "=l"(v) : "f"(x), "f"(y)); return v;
}
__device__ __forceinline__ float2 u2f(u64 v){
    float2 r; asm("mov.b64 {%0, %1}, %2;" : "=f"(r.x), "=f"(r.y) : "l"(v)); return r;
}

// ---------------------------------------------------------------------------
// Convert U and W to bf16 (runs once per launch; 30 MB traffic).
// ---------------------------------------------------------------------------
__global__ void convert_bf16_kernel(const float* __restrict__ U,
                                    const float* __restrict__ W){
    const int NU = MROWS * HDIM / 4;           // 1,048,576 float4s
    int i = blockIdx.x * blockDim.x + threadIdx.x;
    if (i < NU){
        const float4 v = __ldg((const float4*)U + i);
        __nv_bfloat162 lo = __floats2bfloat162_rn(v.x, v.y);
        __nv_bfloat162 hi = __floats2bfloat162_rn(v.z, v.w);
        ((uint2*)g_Ub)[i] = make_uint2(*(unsigned*)&lo, *(unsigned*)&hi);
    } else {
        i -= NU;                               // 0 .. 262143
        const float4 v = __ldg((const float4*)W + i);
        __nv_bfloat162 lo = __floats2bfloat162_rn(v.x, v.y);
        __nv_bfloat162 hi = __floats2bfloat162_rn(v.z, v.w);
        ((uint2*)g_Wb)[i] = make_uint2(*(unsigned*)&lo, *(unsigned*)&hi);
    }
}

// ---------------------------------------------------------------------------
// Precompute per-channel constants (runs once).
// ---------------------------------------------------------------------------
__global__ void precompute_kernel(const float* __restrict__ Alog,
                                  const float* __restrict__ Bp,
                                  const float* __restrict__ Cp){
    const int h = blockIdx.x * blockDim.x + threadIdx.x;
    float am[NST], al2[NST], cs[NST];
    #pragma unroll
    for (int n = 0; n < NST; n++){
        const float A = -expf(Alog[h * NST + n]);
        al2[n] = A * LOG2E;
        am[n]  = exp2f(0.02f * al2[n]);
        cs[n]  = Cp[h * NST + n] * (am[n] - 1.f) * Bp[h * NST + n] / A;
    }
    #pragma unroll
    for (int i = 0; i < 8; i++){
        g_am2T[i * HDIM + h] = f2u(am[2 * i],  am[2 * i + 1]);
        g_al2T[i * HDIM + h] = f2u(al2[2 * i], al2[2 * i + 1]);
        g_c2T [i * HDIM + h] = f2u(cs[2 * i],  cs[2 * i + 1]);
    }
}

// ---------------------------------------------------------------------------
// BF16 tensor-core GEMM: 128x128 tile, BK=64 bf16 (128 B/row — identical smem
// geometry/swizzle/ldmatrix addressing as the TF32 version), 16 kt iterations,
// mma.m16n8k16.bf16 with fp32 accum. log_dt = U·Wᵀ + b; dt = clamp(exp());
// epilogue writes g_du = {dt, u} (u re-read in fp32).
// ---------------------------------------------------------------------------
__device__ __forceinline__ void cp16(float* s, const void* g){
    unsigned sa = (unsigned)__cvta_generic_to_shared(s);
    asm volatile("cp.async.cg.shared.global [%0], [%1], 16;" :: "r"(sa), "l"(g));
}
__device__ __forceinline__ void ldsm4(unsigned* r, unsigned addr){
    asm volatile("ldmatrix.sync.aligned.m8n8.x4.shared.b16 {%0,%1,%2,%3}, [%4];"
        : "=r"(r[0]), "=r"(r[1]), "=r"(r[2]), "=r"(r[3]) : "r"(addr));
}
__device__ __forceinline__ void mma_bf16(float* d, const unsigned* a,
                                         unsigned b0, unsigned b1){
    asm volatile(
        "mma.sync.aligned.m16n8k16.row.col.f32.bf16.bf16.f32 "
        "{%0,%1,%2,%3}, {%4,%5,%6,%7}, {%8,%9}, {%0,%1,%2,%3};"
        : "+f"(d[0]), "+f"(d[1]), "+f"(d[2]), "+f"(d[3])
        : "r"(a[0]), "r"(a[1]), "r"(a[2]), "r"(a[3]), "r"(b0), "r"(b1));
}

__global__ __launch_bounds__(256) void gemm_bf16_kernel(
        const float* __restrict__ U, const float* __restrict__ bias){
    extern __shared__ float smem[];
    const int tid  = threadIdx.x;
    const int lane = tid & 31;
    const int wid  = tid >> 5;
    const int wm   = wid & 1;
    const int wn   = wid >> 1;
    const int bm   = blockIdx.y * 128;
    const int bn   = blockIdx.x * 128;

    float acc[4][4][4];
    #pragma unroll
    for (int i = 0; i < 4; i++)
        #pragma unroll
        for (int j = 0; j < 4; j++)
            #pragma unroll
            for (int r = 0; r < 4; r++) acc[i][j][r] = 0.f;

    const int lrow = tid >> 3;            // 0..31
    const int lkc  = tid & 7;             // 16B chunk within 128B row

    unsigned smemBase = (unsigned)__cvta_generic_to_shared(smem);
    const unsigned aRowOff = (unsigned)((wm * 64 + (lane & 15)) * 128);
    const unsigned bRowOff = (unsigned)((wn * 32 + ((lane & 16) >> 1) + (lane & 7)) * 128);
    int physA[4], physB[4];
    #pragma unroll
    for (int ks = 0; ks < 4; ks++){
        physA[ks] = ((2 * ks + (lane >> 4)) ^ (lane & 7)) * 16;
        physB[ks] = ((2 * ks + ((lane >> 3) & 1)) ^ (lane & 7)) * 16;
    }

    // Per kt: 64 bf16 of K = 128 bytes per row. A/B tiles: 128 rows x 128 B.
    #define LOAD_TILE(KT, STG) do {                                            \
        float* A_s = smem + (STG) * 8192;                                      \
        float* B_s = A_s + 4096;                                               \
        _Pragma("unroll")                                                      \
        for (int i = 0; i < 4; i++){                                           \
            int row  = lrow + i * 32;                                          \
            int phys = lkc ^ (row & 7);                                        \
            cp16(A_s + row * 32 + phys * 4,                                    \
                 (const char*)g_Ub + (size_t)(bm + row) * 2048 + (KT) * 128 + lkc * 16); \
            cp16(B_s + row * 32 + phys * 4,                                    \
                 (const char*)g_Wb + (size_t)(bn + row) * 2048 + (KT) * 128 + lkc * 16); \
        }                                                                      \
        asm volatile("cp.async.commit_group;");                                \
    } while (0)

    LOAD_TILE(0, 0);

    for (int kt = 0; kt < 16; kt++){
        const int cur = kt & 1;
        if (kt < 15) LOAD_TILE(kt + 1, cur ^ 1);
        if (kt < 15) asm volatile("cp.async.wait_group 1;");
        else         asm volatile("cp.async.wait_group 0;");
        __syncthreads();

        unsigned aB = smemBase + cur * 32768 + aRowOff;
        unsigned bB = smemBase + cur * 32768 + 16384 + bRowOff;
        #pragma unroll
        for (int ks = 0; ks < 4; ks++){
            unsigned a[4][4], bb[2][4];
            #pragma unroll
            for (int mt = 0; mt < 4; mt++)
                ldsm4(a[mt], aB + mt * 16 * 128 + physA[ks]);
            #pragma unroll
            for (int tp = 0; tp < 2; tp++)
                ldsm4(bb[tp], bB + tp * 16 * 128 + physB[ks]);
            #pragma unroll
            for (int mt = 0; mt < 4; mt++)
                #pragma unroll
                for (int nt = 0; nt < 4; nt++)
                    mma_bf16(acc[mt][nt], a[mt],
                             bb[nt >> 1][(nt & 1) * 2], bb[nt >> 1][(nt & 1) * 2 + 1]);
        }
        __syncthreads();
    }

    const int rbase = bm + wm * 64 + (lane >> 2);
    const int gbase = bn + wn * 32 + 2 * (lane & 3);
    float bv[4][2];
    #pragma unroll
    for (int nt = 0; nt < 4; nt++){
        bv[nt][0] = __ldg(bias + gbase + nt * 8);
        bv[nt][1] = __ldg(bias + gbase + nt * 8 + 1);
    }
    #pragma unroll
    for (int mt = 0; mt < 4; mt++)
        #pragma unroll
        for (int nt = 0; nt < 4; nt++)
            #pragma unroll
            for (int rr = 0; rr < 2; rr++){
                const int m = rbase + mt * 16 + rr * 8;
                const int g0 = gbase + nt * 8;
                float v0 = acc[mt][nt][rr * 2]     + bv[nt][0];
                float v1 = acc[mt][nt][rr * 2 + 1] + bv[nt][1];
                v0 = fminf(fmaxf(__expf(v0), DT_MIN_V), DT_MAX_V);
                v1 = fminf(fmaxf(__expf(v1), DT_MIN_V), DT_MAX_V);
                const float2 uv = *(const float2*)&U[(size_t)m * HDIM + g0];
                float4 w;
                w.x = v0; w.y = uv.x;
                w.z = v1; w.w = uv.y;
                *(float4*)&g_du[(size_t)m * HDIM + g0] = w;
            }
}

// ---------------------------------------------------------------------------
// Step macros (register-only, fully inline).
// ---------------------------------------------------------------------------
#define FAST_STEP(uu) do {                                                     \
    const u64 _u2 = f2u((uu), (uu));                                           \
    _Pragma("unroll")                                                          \
    for (int _i = 0; _i < 8; _i++) x2[_i] = ffma2(x2[_i], am2[_i], _u2);       \
} while (0)

#define SLOW_STEP(dtv, uv) do {                                                \
    _Pragma("unroll")                                                          \
    for (int _i = 0; _i < 8; _i++){                                            \
        float2 _xv = u2f(x2[_i]);                                              \
        const float2 _av = u2f(am2[_i]);                                       \
        const float2 _lv = u2f(al2[_i]);                                       \
        {                                                                      \
            const float _ab = exp2f((dtv) * _lv.x);                            \
            _xv.x = fmaf(_xv.x, _ab, (_ab - 1.f) / (_av.x - 1.f) * (uv));      \
        }                                                                      \
        {                                                                      \
            const float _ab = exp2f((dtv) * _lv.y);                            \
            _xv.y = fmaf(_xv.y, _ab, (_ab - 1.f) / (_av.y - 1.f) * (uv));      \
        }                                                                      \
        x2[_i] = f2u(_xv.x, _xv.y);                                            \
    }                                                                          \
} while (0)

// ---------------------------------------------------------------------------
// Pass 1: per-(channel, group) reduce over 128 steps -> (Pg, Sg).
// ---------------------------------------------------------------------------
__global__ __launch_bounds__(128) void scan_reduce_kernel(){
    const int tid = threadIdx.x;
    const int s = blockIdx.x * 128 + tid;
    const int g = blockIdx.y;
    const int b = s >> 10;
    const int h = s & 1023;

    u64 am2[8], al2[8], x2[8];
    #pragma unroll
    for (int i = 0; i < 8; i++){
        am2[i] = g_am2T[i * HDIM + h];
        al2[i] = g_al2T[i * HDIM + h];
        x2[i] = 0ull;
    }

    const size_t base = ((size_t)(b * LSEQ + g * GLEN)) * HDIM + h;
    float dtsum = 0.f;

    #pragma unroll 1
    for (int bt = 0; bt < NB; bt++){
        float2 d[16];
        #pragma unroll
        for (int j = 0; j < 16; j++)
            d[j] = __ldg((const float2*)&g_du[base + (size_t)(bt * 16 + j) * HDIM]);
        bool fast = true;
        #pragma unroll
        for (int j = 0; j < 16; j++){ fast &= (d[j].x == DT_MAX_V); dtsum += d[j].x; }
        if (fast){
            #pragma unroll
            for (int j = 0; j < 16; j++) FAST_STEP(d[j].y);
        } else {
            #pragma unroll
            for (int j = 0; j < 16; j++){
                if (d[j].x == DT_MAX_V) FAST_STEP(d[j].y);
                else                    SLOW_STEP(d[j].x, d[j].y);
            }
        }
    }

    float* Pp = g_Pg + (size_t)g * NST * NCH + s;
    float* Sp = g_Sg + (size_t)g * NST * NCH + s;
    #pragma unroll
    for (int i = 0; i < 8; i++){
        const float2 lv = u2f(al2[i]);
        const float2 xv = u2f(x2[i]);
        Pp[(size_t)(2 * i)     * NCH] = exp2f(lv.x * dtsum);
        Pp[(size_t)(2 * i + 1) * NCH] = exp2f(lv.y * dtsum);
        Sp[(size_t)(2 * i)     * NCH] = xv.x;
        Sp[(size_t)(2 * i + 1) * NCH] = xv.y;
    }
}

// ---------------------------------------------------------------------------
// Pass 2: fold 16 group aggregates -> group start states Xg.
// ---------------------------------------------------------------------------
#define STRIDE4 (NST*NCH/4)
__global__ void scan_stitch_kernel(){
    const int id = blockIdx.x * blockDim.x + threadIdx.x;  // 0..8191
    const float4* Pg4 = (const float4*)g_Pg;
    const float4* Sg4 = (const float4*)g_Sg;
    float4* Xg4 = (float4*)g_Xg;
    float4 Pg[NGRP], Sg[NGRP];
    #pragma unroll
    for (int g = 0; g < NGRP; g++){
        Pg[g] = Pg4[(size_t)g * STRIDE4 + id];
        Sg[g] = Sg4[(size_t)g * STRIDE4 + id];
    }
    float4 x = make_float4(0.f, 0.f, 0.f, 0.f);
    #pragma unroll
    for (int g = 0; g < NGRP; g++){
        Xg4[(size_t)g * STRIDE4 + id] = x;
        x.x = fmaf(Pg[g].x, x.x, Sg[g].x);
        x.y = fmaf(Pg[g].y, x.y, Sg[g].y);
        x.z = fmaf(Pg[g].z, x.z, Sg[g].z);
        x.w = fmaf(Pg[g].w, x.w, Sg[g].w);
    }
}

// ---------------------------------------------------------------------------
// Pass 3: final scan + output. Thread = (channel, group); 128 steps from Xg.
// ---------------------------------------------------------------------------
__global__ __launch_bounds__(128) void scan_final_kernel(
        const float* __restrict__ Dp, float* __restrict__ out){
    const int tid = threadIdx.x;
    const int s = blockIdx.x * 128 + tid;
    const int g = blockIdx.y;
    const int b = s >> 10;
    const int h = s & 1023;

    u64 am2[8], c2[8], x2[8];
    #pragma unroll
    for (int i = 0; i < 8; i++){
        am2[i] = g_am2T[i * HDIM + h];
        c2[i]  = g_c2T [i * HDIM + h];
    }
    const float Dh = __ldg(Dp + h);

    {
        const float* Xp = g_Xg + (size_t)g * NST * NCH + s;
        #pragma unroll
        for (int i = 0; i < 8; i++)
            x2[i] = f2u(Xp[(size_t)(2 * i) * NCH], Xp[(size_t)(2 * i + 1) * NCH]);
    }

    const size_t base = ((size_t)(b * LSEQ + g * GLEN)) * HDIM + h;
    float* op = out + base;

    #define Y_EMIT(j, uv) do {                                                 \
        u64 ya = 0ull, yb = 0ull;                                              \
        _Pragma("unroll")                                                      \
        for (int _i = 0; _i < 4; _i++) ya = ffma2(c2[_i], x2[_i], ya);         \
        _Pragma("unroll")                                                      \
        for (int _i = 4; _i < 8; _i++) yb = ffma2(c2[_i], x2[_i], yb);         \
        const float2 _va = u2f(ya);                                            \
        const float2 _vb = u2f(yb);                                            \
        op[(size_t)(j) * HDIM] = fmaf(Dh, (uv), (_va.x + _va.y) + (_vb.x + _vb.y)); \
    } while (0)

    #pragma unroll 1
    for (int bt = 0; bt < NB; bt++){
        float2 d[16];
        #pragma unroll
        for (int j = 0; j < 16; j++)
            d[j] = __ldg((const float2*)&g_du[base + (size_t)(bt * 16 + j) * HDIM]);
        bool fast = true;
        #pragma unroll
        for (int j = 0; j < 16; j++) fast &= (d[j].x == DT_MAX_V);
        if (fast){
            #pragma unroll
            for (int j = 0; j < 16; j++){
                FAST_STEP(d[j].y);
                Y_EMIT(bt * 16 + j, d[j].y);
            }
        } else {
            u64 al2[8];
            #pragma unroll
            for (int i = 0; i < 8; i++) al2[i] = g_al2T[i * HDIM + h];
            #pragma unroll
            for (int j = 0; j < 16; j++){
                if (d[j].x == DT_MAX_V) FAST_STEP(d[j].y);
                else                    SLOW_STEP(d[j].x, d[j].y);
                Y_EMIT(bt * 16 + j, d[j].y);
            }
        }
    }
    #undef Y_EMIT
}

// ---------------------------------------------------------------------------
extern "C" void kernel_launch(void* const* d_in, const int* in_sizes, int n_in,
                              void* d_out, int out_size){
    const float* u    = (const float*)d_in[0];
    const float* Alog = (const float*)d_in[1];
    const float* Bp   = (const float*)d_in[2];
    const float* Cp   = (const float*)d_in[3];
    const float* Dp   = (const float*)d_in[4];
    const float* Wdt  = (const float*)d_in[5];
    const float* bdt  = (const float*)d_in[6];
    float* out = (float*)d_out;

    cudaFuncSetAttribute(gemm_bf16_kernel,
                         cudaFuncAttributeMaxDynamicSharedMemorySize, 65536);

    convert_bf16_kernel<<<(MROWS * HDIM / 4 + HDIM * HDIM / 4) / 256, 256>>>(u, Wdt);
    precompute_kernel<<<HDIM / 128, 128>>>(Alog, Bp, Cp);

    dim3 ggrid(HDIM / 128, MROWS / 128);            // (8, 32)
    gemm_bf16_kernel<<<ggrid, 256, 65536>>>(u, bdt);

    scan_reduce_kernel<<<dim3(NCH / 128, NGRP), 128>>>();
    scan_stitch_kernel<<<STRIDE4 / 256, 256>>>();
    scan_final_kernel<<<dim3(NCH / 128, NGRP), 128>>>(Dp, out);
}

// round 11
// speedup vs baseline: 1.4215x; 1.0263x over previous
#include <cuda_runtime.h>
#include <cuda_bf16.h>

#define BATCH 2
#define LSEQ 2048
#define HDIM 1024
#define NST 16
#define MROWS (BATCH*LSEQ)     // 4096
#define DT_MIN_V 0.001f
#define DT_MAX_V 0.02f
#define NGRP 32
#define GLEN (LSEQ/NGRP)       // 64 steps per group
#define NB (GLEN/16)           // 4 batches of 16
#define NCH (BATCH*HDIM)       // 2048
#define LOG2E 1.4426950408889634f

typedef unsigned long long u64;

// Scratch (__device__ globals: allocation-free rule)
__device__ float2 g_du[BATCH*LSEQ*HDIM];       // (B,L,H) packed {dt, u}
__device__ __nv_bfloat16 g_Ub[MROWS*HDIM];     // bf16 copy of u (GEMM A)
__device__ __nv_bfloat16 g_Wb[HDIM*HDIM];      // bf16 copy of W_dt (GEMM B)
// group-level aggregates / start states, layout [group][n][s]
__device__ float  g_Pg [NGRP*NST*NCH];
__device__ float  g_Sg [NGRP*NST*NCH];
__device__ float  g_Xg [NGRP*NST*NCH];
// Per-channel constant tables, packed pairs, layout [pair i][h]
__device__ u64 g_am2T[8*HDIM];
__device__ u64 g_al2T[8*HDIM];
__device__ u64 g_c2T [8*HDIM];

__device__ __forceinline__ u64 ffma2(u64 a, u64 b, u64 c){
    u64 d;
    asm("fma.rn.f32x2 %0, %1, %2, %3;" : "=l"(d) : "l"(a), "l"(b), "l"(c));
    return d;
}
__device__ __forceinline__ u64 f2u(float x, float y){
    u64 v; asm("mov.b64 %0, {%1, %2};" : "=l"(v) : "f"(x), "f"(y)); return v;
}
__device__ __forceinline__ float2 u2f(u64 v){
    float2 r; asm("mov.b64 {%0, %1}, %2;" : "=f"(r.x), "=f"(r.y) : "l"(v)); return r;
}

// ---------------------------------------------------------------------------
// Convert U and W to bf16 (runs once per launch; ~30 MB traffic).
// ---------------------------------------------------------------------------
__global__ void convert_bf16_kernel(const float* __restrict__ U,
                                    const float* __restrict__ W){
    const int NU = MROWS * HDIM / 4;
    int i = blockIdx.x * blockDim.x + threadIdx.x;
    if (i < NU){
        const float4 v = __ldg((const float4*)U + i);
        __nv_bfloat162 lo = __floats2bfloat162_rn(v.x, v.y);
        __nv_bfloat162 hi = __floats2bfloat162_rn(v.z, v.w);
        ((uint2*)g_Ub)[i] = make_uint2(*(unsigned*)&lo, *(unsigned*)&hi);
    } else {
        i -= NU;
        const float4 v = __ldg((const float4*)W + i);
        __nv_bfloat162 lo = __floats2bfloat162_rn(v.x, v.y);
        __nv_bfloat162 hi = __floats2bfloat162_rn(v.z, v.w);
        ((uint2*)g_Wb)[i] = make_uint2(*(unsigned*)&lo, *(unsigned*)&hi);
    }
}

// ---------------------------------------------------------------------------
// Precompute per-channel constants (runs once).
// ---------------------------------------------------------------------------
__global__ void precompute_kernel(const float* __restrict__ Alog,
                                  const float* __restrict__ Bp,
                                  const float* __restrict__ Cp){
    const int h = blockIdx.x * blockDim.x + threadIdx.x;
    float am[NST], al2[NST], cs[NST];
    #pragma unroll
    for (int n = 0; n < NST; n++){
        const float A = -expf(Alog[h * NST + n]);
        al2[n] = A * LOG2E;
        am[n]  = exp2f(0.02f * al2[n]);
        cs[n]  = Cp[h * NST + n] * (am[n] - 1.f) * Bp[h * NST + n] / A;
    }
    #pragma unroll
    for (int i = 0; i < 8; i++){
        g_am2T[i * HDIM + h] = f2u(am[2 * i],  am[2 * i + 1]);
        g_al2T[i * HDIM + h] = f2u(al2[2 * i], al2[2 * i + 1]);
        g_c2T [i * HDIM + h] = f2u(cs[2 * i],  cs[2 * i + 1]);
    }
}

// ---------------------------------------------------------------------------
// BF16 tensor-core GEMM: 128x256 block tile (grid = 128 blocks = ONE wave),
// BK=64 bf16 (128 B/row), 16 kt iterations, mma.m16n8k16.bf16, fp32 accum.
// 8 warps, warp tile 64x64. Epilogue: dt = clamp(exp(acc+b)); g_du = {dt,u}.
// ---------------------------------------------------------------------------
__device__ __forceinline__ void cp16(float* s, const void* g){
    unsigned sa = (unsigned)__cvta_generic_to_shared(s);
    asm volatile("cp.async.cg.shared.global [%0], [%1], 16;" :: "r"(sa), "l"(g));
}
__device__ __forceinline__ void ldsm4(unsigned* r, unsigned addr){
    asm volatile("ldmatrix.sync.aligned.m8n8.x4.shared.b16 {%0,%1,%2,%3}, [%4];"
        : "=r"(r[0]), "=r"(r[1]), "=r"(r[2]), "=r"(r[3]) : "r"(addr));
}
__device__ __forceinline__ void mma_bf16(float* d, const unsigned* a,
                                         unsigned b0, unsigned b1){
    asm volatile(
        "mma.sync.aligned.m16n8k16.row.col.f32.bf16.bf16.f32 "
        "{%0,%1,%2,%3}, {%4,%5,%6,%7}, {%8,%9}, {%0,%1,%2,%3};"
        : "+f"(d[0]), "+f"(d[1]), "+f"(d[2]), "+f"(d[3])
        : "r"(a[0]), "r"(a[1]), "r"(a[2]), "r"(a[3]), "r"(b0), "r"(b1));
}

#define GEMM_SMEM_STG 12288      // floats per stage: (128+256) rows * 32
#define GEMM_B_OFF    4096       // floats: A tile = 128 rows * 32

__global__ __launch_bounds__(256, 1) void gemm_bf16_kernel(
        const float* __restrict__ U, const float* __restrict__ bias){
    extern __shared__ float smem[];
    const int tid  = threadIdx.x;
    const int lane = tid & 31;
    const int wid  = tid >> 5;
    const int wm   = wid & 1;             // 2 warps along M (64 each)
    const int wn   = wid >> 1;            // 4 warps along N (64 each)
    const int bm   = blockIdx.y * 128;
    const int bn   = blockIdx.x * 256;

    float acc[4][8][4];
    #pragma unroll
    for (int i = 0; i < 4; i++)
        #pragma unroll
        for (int j = 0; j < 8; j++)
            #pragma unroll
            for (int r = 0; r < 4; r++) acc[i][j][r] = 0.f;

    const int lrow = tid >> 3;            // 0..31
    const int lkc  = tid & 7;             // 16B chunk within 128B row

    unsigned smemBase = (unsigned)__cvta_generic_to_shared(smem);
    const unsigned aRowOff = (unsigned)((wm * 64 + (lane & 15)) * 128);
    const unsigned bRowOff = (unsigned)((wn * 64 + ((lane & 16) >> 1) + (lane & 7)) * 128);
    int physA[4], physB[4];
    #pragma unroll
    for (int ks = 0; ks < 4; ks++){
        physA[ks] = ((2 * ks + (lane >> 4)) ^ (lane & 7)) * 16;
        physB[ks] = ((2 * ks + ((lane >> 3) & 1)) ^ (lane & 7)) * 16;
    }

    #define LOAD_TILE(KT, STG) do {                                            \
        float* A_s = smem + (STG) * GEMM_SMEM_STG;                             \
        float* B_s = A_s + GEMM_B_OFF;                                         \
        _Pragma("unroll")                                                      \
        for (int i = 0; i < 4; i++){                                           \
            int row  = lrow + i * 32;                                          \
            int phys = lkc ^ (row & 7);                                        \
            cp16(A_s + row * 32 + phys * 4,                                    \
                 (const char*)g_Ub + (size_t)(bm + row) * 2048 + (KT) * 128 + lkc * 16); \
        }                                                                      \
        _Pragma("unroll")                                                      \
        for (int i = 0; i < 8; i++){                                           \
            int row  = lrow + i * 32;                                          \
            int phys = lkc ^ (row & 7);                                        \
            cp16(B_s + row * 32 + phys * 4,                                    \
                 (const char*)g_Wb + (size_t)(bn + row) * 2048 + (KT) * 128 + lkc * 16); \
        }                                                                      \
        asm volatile("cp.async.commit_group;");                                \
    } while (0)

    LOAD_TILE(0, 0);

    for (int kt = 0; kt < 16; kt++){
        const int cur = kt & 1;
        if (kt < 15) LOAD_TILE(kt + 1, cur ^ 1);
        if (kt < 15) asm volatile("cp.async.wait_group 1;");
        else         asm volatile("cp.async.wait_group 0;");
        __syncthreads();

        unsigned aB = smemBase + cur * (GEMM_SMEM_STG * 4) + aRowOff;
        unsigned bB = smemBase + cur * (GEMM_SMEM_STG * 4) + GEMM_B_OFF * 4 + bRowOff;
        #pragma unroll
        for (int ks = 0; ks < 4; ks++){
            unsigned a[4][4], bb[4][4];
            #pragma unroll
            for (int mt = 0; mt < 4; mt++)
                ldsm4(a[mt], aB + mt * 16 * 128 + physA[ks]);
            #pragma unroll
            for (int tp = 0; tp < 4; tp++)
                ldsm4(bb[tp], bB + tp * 16 * 128 + physB[ks]);
            #pragma unroll
            for (int mt = 0; mt < 4; mt++)
                #pragma unroll
                for (int nt = 0; nt < 8; nt++)
                    mma_bf16(acc[mt][nt], a[mt],
                             bb[nt >> 1][(nt & 1) * 2], bb[nt >> 1][(nt & 1) * 2 + 1]);
        }
        __syncthreads();
    }

    const int rbase = bm + wm * 64 + (lane >> 2);
    const int gbase = bn + wn * 64 + 2 * (lane & 3);
    float bv[8][2];
    #pragma unroll
    for (int nt = 0; nt < 8; nt++){
        bv[nt][0] = __ldg(bias + gbase + nt * 8);
        bv[nt][1] = __ldg(bias + gbase + nt * 8 + 1);
    }
    #pragma unroll
    for (int mt = 0; mt < 4; mt++)
        #pragma unroll
        for (int nt = 0; nt < 8; nt++)
            #pragma unroll
            for (int rr = 0; rr < 2; rr++){
                const int m = rbase + mt * 16 + rr * 8;
                const int g0 = gbase + nt * 8;
                float v0 = acc[mt][nt][rr * 2]     + bv[nt][0];
                float v1 = acc[mt][nt][rr * 2 + 1] + bv[nt][1];
                v0 = fminf(fmaxf(__expf(v0), DT_MIN_V), DT_MAX_V);
                v1 = fminf(fmaxf(__expf(v1), DT_MIN_V), DT_MAX_V);
                const float2 uv = *(const float2*)&U[(size_t)m * HDIM + g0];
                float4 w;
                w.x = v0; w.y = uv.x;
                w.z = v1; w.w = uv.y;
                *(float4*)&g_du[(size_t)m * HDIM + g0] = w;
            }
}

// ---------------------------------------------------------------------------
// Step macros (register-only, fully inline).
// ---------------------------------------------------------------------------
#define FAST_STEP(uu) do {                                                     \
    const u64 _u2 = f2u((uu), (uu));                                           \
    _Pragma("unroll")                                                          \
    for (int _i = 0; _i < 8; _i++) x2[_i] = ffma2(x2[_i], am2[_i], _u2);       \
} while (0)

#define SLOW_STEP(dtv, uv) do {                                                \
    _Pragma("unroll")                                                          \
    for (int _i = 0; _i < 8; _i++){                                            \
        float2 _xv = u2f(x2[_i]);                                              \
        const float2 _av = u2f(am2[_i]);                                       \
        const float2 _lv = u2f(al2[_i]);                                       \
        {                                                                      \
            const float _ab = exp2f((dtv) * _lv.x);                            \
            _xv.x = fmaf(_xv.x, _ab, (_ab - 1.f) / (_av.x - 1.f) * (uv));      \
        }                                                                      \
        {                                                                      \
            const float _ab = exp2f((dtv) * _lv.y);                            \
            _xv.y = fmaf(_xv.y, _ab, (_ab - 1.f) / (_av.y - 1.f) * (uv));      \
        }                                                                      \
        x2[_i] = f2u(_xv.x, _xv.y);                                            \
    }                                                                          \
} while (0)

// ---------------------------------------------------------------------------
// Pass 1: per-(channel, group) reduce over 64 steps -> (Pg, Sg).
// ---------------------------------------------------------------------------
__global__ __launch_bounds__(128) void scan_reduce_kernel(){
    const int tid = threadIdx.x;
    const int s = blockIdx.x * 128 + tid;
    const int g = blockIdx.y;
    const int b = s >> 10;
    const int h = s & 1023;

    u64 am2[8], al2[8], x2[8];
    #pragma unroll
    for (int i = 0; i < 8; i++){
        am2[i] = g_am2T[i * HDIM + h];
        al2[i] = g_al2T[i * HDIM + h];
        x2[i] = 0ull;
    }

    const size_t base = ((size_t)(b * LSEQ + g * GLEN)) * HDIM + h;
    float dtsum = 0.f;

    #pragma unroll 1
    for (int bt = 0; bt < NB; bt++){
        float2 d[16];
        #pragma unroll
        for (int j = 0; j < 16; j++)
            d[j] = __ldg((const float2*)&g_du[base + (size_t)(bt * 16 + j) * HDIM]);
        bool fast = true;
        #pragma unroll
        for (int j = 0; j < 16; j++){ fast &= (d[j].x == DT_MAX_V); dtsum += d[j].x; }
        if (fast){
            #pragma unroll
            for (int j = 0; j < 16; j++) FAST_STEP(d[j].y);
        } else {
            #pragma unroll
            for (int j = 0; j < 16; j++){
                if (d[j].x == DT_MAX_V) FAST_STEP(d[j].y);
                else                    SLOW_STEP(d[j].x, d[j].y);
            }
        }
    }

    float* Pp = g_Pg + (size_t)g * NST * NCH + s;
    float* Sp = g_Sg + (size_t)g * NST * NCH + s;
    #pragma unroll
    for (int i = 0; i < 8; i++){
        const float2 lv = u2f(al2[i]);
        const float2 xv = u2f(x2[i]);
        Pp[(size_t)(2 * i)     * NCH] = exp2f(lv.x * dtsum);
        Pp[(size_t)(2 * i + 1) * NCH] = exp2f(lv.y * dtsum);
        Sp[(size_t)(2 * i)     * NCH] = xv.x;
        Sp[(size_t)(2 * i + 1) * NCH] = xv.y;
    }
}

// ---------------------------------------------------------------------------
// Pass 2: fold 32 group aggregates -> group start states Xg.
// 4 rounds of (8 batched loads + 8 sequential folds).
// ---------------------------------------------------------------------------
#define STRIDE4 (NST*NCH/4)
__global__ void scan_stitch_kernel(){
    const int id = blockIdx.x * blockDim.x + threadIdx.x;  // 0..8191
    const float4* Pg4 = (const float4*)g_Pg;
    const float4* Sg4 = (const float4*)g_Sg;
    float4* Xg4 = (float4*)g_Xg;
    float4 x = make_float4(0.f, 0.f, 0.f, 0.f);
    #pragma unroll 1
    for (int r = 0; r < NGRP / 8; r++){
        float4 Pg[8], Sg[8];
        #pragma unroll
        for (int c = 0; c < 8; c++){
            Pg[c] = Pg4[(size_t)(r * 8 + c) * STRIDE4 + id];
            Sg[c] = Sg4[(size_t)(r * 8 + c) * STRIDE4 + id];
        }
        #pragma unroll
        for (int c = 0; c < 8; c++){
            Xg4[(size_t)(r * 8 + c) * STRIDE4 + id] = x;
            x.x = fmaf(Pg[c].x, x.x, Sg[c].x);
            x.y = fmaf(Pg[c].y, x.y, Sg[c].y);
            x.z = fmaf(Pg[c].z, x.z, Sg[c].z);
            x.w = fmaf(Pg[c].w, x.w, Sg[c].w);
        }
    }
}

// ---------------------------------------------------------------------------
// Pass 3: final scan + output. Thread = (channel, group); 64 steps from Xg.
// ---------------------------------------------------------------------------
__global__ __launch_bounds__(128) void scan_final_kernel(
        const float* __restrict__ Dp, float* __restrict__ out){
    const int tid = threadIdx.x;
    const int s = blockIdx.x * 128 + tid;
    const int g = blockIdx.y;
    const int b = s >> 10;
    const int h = s & 1023;

    u64 am2[8], c2[8], x2[8];
    #pragma unroll
    for (int i = 0; i < 8; i++){
        am2[i] = g_am2T[i * HDIM + h];
        c2[i]  = g_c2T [i * HDIM + h];
    }
    const float Dh = __ldg(Dp + h);

    {
        const float* Xp = g_Xg + (size_t)g * NST * NCH + s;
        #pragma unroll
        for (int i = 0; i < 8; i++)
            x2[i] = f2u(Xp[(size_t)(2 * i) * NCH], Xp[(size_t)(2 * i + 1) * NCH]);
    }

    const size_t base = ((size_t)(b * LSEQ + g * GLEN)) * HDIM + h;
    float* op = out + base;

    #define Y_EMIT(j, uv) do {                                                 \
        u64 ya = 0ull, yb = 0ull;                                              \
        _Pragma("unroll")                                                      \
        for (int _i = 0; _i < 4; _i++) ya = ffma2(c2[_i], x2[_i], ya);         \
        _Pragma("unroll")                                                      \
        for (int _i = 4; _i < 8; _i++) yb = ffma2(c2[_i], x2[_i], yb);         \
        const float2 _va = u2f(ya);                                            \
        const float2 _vb = u2f(yb);                                            \
        op[(size_t)(j) * HDIM] = fmaf(Dh, (uv), (_va.x + _va.y) + (_vb.x + _vb.y)); \
    } while (0)

    #pragma unroll 1
    for (int bt = 0; bt < NB; bt++){
        float2 d[16];
        #pragma unroll
        for (int j = 0; j < 16; j++)
            d[j] = __ldg((const float2*)&g_du[base + (size_t)(bt * 16 + j) * HDIM]);
        bool fast = true;
        #pragma unroll
        for (int j = 0; j < 16; j++) fast &= (d[j].x == DT_MAX_V);
        if (fast){
            #pragma unroll
            for (int j = 0; j < 16; j++){
                FAST_STEP(d[j].y);
                Y_EMIT(bt * 16 + j, d[j].y);
            }
        } else {
            u64 al2[8];
            #pragma unroll
            for (int i = 0; i < 8; i++) al2[i] = g_al2T[i * HDIM + h];
            #pragma unroll
            for (int j = 0; j < 16; j++){
                if (d[j].x == DT_MAX_V) FAST_STEP(d[j].y);
                else                    SLOW_STEP(d[j].x, d[j].y);
                Y_EMIT(bt * 16 + j, d[j].y);
            }
        }
    }
    #undef Y_EMIT
}

// ---------------------------------------------------------------------------
extern "C" void kernel_launch(void* const* d_in, const int* in_sizes, int n_in,
                              void* d_out, int out_size){
    const float* u    = (const float*)d_in[0];
    const float* Alog = (const float*)d_in[1];
    const float* Bp   = (const float*)d_in[2];
    const float* Cp   = (const float*)d_in[3];
    const float* Dp   = (const float*)d_in[4];
    const float* Wdt  = (const float*)d_in[5];
    const float* bdt  = (const float*)d_in[6];
    float* out = (float*)d_out;

    cudaFuncSetAttribute(gemm_bf16_kernel,
                         cudaFuncAttributeMaxDynamicSharedMemorySize, 98304);

    convert_bf16_kernel<<<(MROWS * HDIM / 4 + HDIM * HDIM / 4) / 256, 256>>>(u, Wdt);
    precompute_kernel<<<HDIM / 128, 128>>>(Alog, Bp, Cp);

    dim3 ggrid(HDIM / 256, MROWS / 128);            // (4, 32) = 128 blocks
    gemm_bf16_kernel<<<ggrid, 256, 98304>>>(u, bdt);

    scan_reduce_kernel<<<dim3(NCH / 128, NGRP), 128>>>();
    scan_stitch_kernel<<<STRIDE4 / 256, 256>>>();
    scan_final_kernel<<<dim3(NCH / 128, NGRP), 128>>>(Dp, out);
}

// round 12
// speedup vs baseline: 1.5089x; 1.0615x over previous
#include <cuda_runtime.h>
#include <cuda_bf16.h>

#define BATCH 2
#define LSEQ 2048
#define HDIM 1024
#define NST 16
#define MROWS (BATCH*LSEQ)     // 4096
#define DT_MIN_V 0.001f
#define DT_MAX_V 0.02f
#define NGRP 32
#define GLEN (LSEQ/NGRP)       // 64 steps per group
#define NB (GLEN/16)           // 4 batches of 16
#define NCH (BATCH*HDIM)       // 2048
#define LOG2E 1.4426950408889634f

typedef unsigned long long u64;

// Scratch (__device__ globals: allocation-free rule)
__device__ float g_dtv[BATCH*LSEQ*HDIM];       // (B,L,H) clamped dt (fp32)
__device__ __nv_bfloat16 g_Ub[MROWS*HDIM];     // bf16 copy of u (GEMM A)
__device__ __nv_bfloat16 g_Wb[HDIM*HDIM];      // bf16 copy of W_dt (GEMM B)
// group-level aggregates / start states, layout [group][n][s]
__device__ float  g_Pg [NGRP*NST*NCH];
__device__ float  g_Sg [NGRP*NST*NCH];
__device__ float  g_Xg [NGRP*NST*NCH];
// Per-channel constant tables, packed pairs, layout [pair i][h]
__device__ u64 g_am2T[8*HDIM];
__device__ u64 g_al2T[8*HDIM];
__device__ u64 g_c2T [8*HDIM];

__device__ __forceinline__ u64 ffma2(u64 a, u64 b, u64 c){
    u64 d;
    asm("fma.rn.f32x2 %0, %1, %2, %3;" : "=l"(d) : "l"(a), "l"(b), "l"(c));
    return d;
}
__device__ __forceinline__ u64 f2u(float x, float y){
    u64 v; asm("mov.b64 %0, {%1, %2};" : "=l"(v) : "f"(x), "f"(y)); return v;
}
__device__ __forceinline__ float2 u2f(u64 v){
    float2 r; asm("mov.b64 {%0, %1}, %2;" : "=f"(r.x), "=f"(r.y) : "l"(v)); return r;
}

// ---------------------------------------------------------------------------
// Convert U and W to bf16 (runs once per launch).
// ---------------------------------------------------------------------------
__global__ void convert_bf16_kernel(const float* __restrict__ U,
                                    const float* __restrict__ W){
    const int NU = MROWS * HDIM / 4;
    int i = blockIdx.x * blockDim.x + threadIdx.x;
    if (i < NU){
        const float4 v = __ldg((const float4*)U + i);
        __nv_bfloat162 lo = __floats2bfloat162_rn(v.x, v.y);
        __nv_bfloat162 hi = __floats2bfloat162_rn(v.z, v.w);
        ((uint2*)g_Ub)[i] = make_uint2(*(unsigned*)&lo, *(unsigned*)&hi);
    } else {
        i -= NU;
        const float4 v = __ldg((const float4*)W + i);
        __nv_bfloat162 lo = __floats2bfloat162_rn(v.x, v.y);
        __nv_bfloat162 hi = __floats2bfloat162_rn(v.z, v.w);
        ((uint2*)g_Wb)[i] = make_uint2(*(unsigned*)&lo, *(unsigned*)&hi);
    }
}

// ---------------------------------------------------------------------------
// Precompute per-channel constants (runs once).
// ---------------------------------------------------------------------------
__global__ void precompute_kernel(const float* __restrict__ Alog,
                                  const float* __restrict__ Bp,
                                  const float* __restrict__ Cp){
    const int h = blockIdx.x * blockDim.x + threadIdx.x;
    float am[NST], al2[NST], cs[NST];
    #pragma unroll
    for (int n = 0; n < NST; n++){
        const float A = -expf(Alog[h * NST + n]);
        al2[n] = A * LOG2E;
        am[n]  = exp2f(0.02f * al2[n]);
        cs[n]  = Cp[h * NST + n] * (am[n] - 1.f) * Bp[h * NST + n] / A;
    }
    #pragma unroll
    for (int i = 0; i < 8; i++){
        g_am2T[i * HDIM + h] = f2u(am[2 * i],  am[2 * i + 1]);
        g_al2T[i * HDIM + h] = f2u(al2[2 * i], al2[2 * i + 1]);
        g_c2T [i * HDIM + h] = f2u(cs[2 * i],  cs[2 * i + 1]);
    }
}

// ---------------------------------------------------------------------------
// BF16 tensor-core GEMM: 128x256 block tile (grid = 128 blocks = one wave),
// BK=64 bf16 (128 B/row), 16 kt, mma.m16n8k16.bf16, fp32 accum.
// Epilogue: dt = clamp(exp(acc+b)) -> g_dtv (fp32, float2 stores).
// ---------------------------------------------------------------------------
__device__ __forceinline__ void cp16(float* s, const void* g){
    unsigned sa = (unsigned)__cvta_generic_to_shared(s);
    asm volatile("cp.async.cg.shared.global [%0], [%1], 16;" :: "r"(sa), "l"(g));
}
__device__ __forceinline__ void ldsm4(unsigned* r, unsigned addr){
    asm volatile("ldmatrix.sync.aligned.m8n8.x4.shared.b16 {%0,%1,%2,%3}, [%4];"
        : "=r"(r[0]), "=r"(r[1]), "=r"(r[2]), "=r"(r[3]) : "r"(addr));
}
__device__ __forceinline__ void mma_bf16(float* d, const unsigned* a,
                                         unsigned b0, unsigned b1){
    asm volatile(
        "mma.sync.aligned.m16n8k16.row.col.f32.bf16.bf16.f32 "
        "{%0,%1,%2,%3}, {%4,%5,%6,%7}, {%8,%9}, {%0,%1,%2,%3};"
        : "+f"(d[0]), "+f"(d[1]), "+f"(d[2]), "+f"(d[3])
        : "r"(a[0]), "r"(a[1]), "r"(a[2]), "r"(a[3]), "r"(b0), "r"(b1));
}

#define GEMM_SMEM_STG 12288      // floats per stage: (128+256) rows * 32
#define GEMM_B_OFF    4096       // floats: A tile = 128 rows * 32

__global__ __launch_bounds__(256, 1) void gemm_bf16_kernel(
        const float* __restrict__ bias){
    extern __shared__ float smem[];
    const int tid  = threadIdx.x;
    const int lane = tid & 31;
    const int wid  = tid >> 5;
    const int wm   = wid & 1;
    const int wn   = wid >> 1;
    const int bm   = blockIdx.y * 128;
    const int bn   = blockIdx.x * 256;

    float acc[4][8][4];
    #pragma unroll
    for (int i = 0; i < 4; i++)
        #pragma unroll
        for (int j = 0; j < 8; j++)
            #pragma unroll
            for (int r = 0; r < 4; r++) acc[i][j][r] = 0.f;

    const int lrow = tid >> 3;
    const int lkc  = tid & 7;

    unsigned smemBase = (unsigned)__cvta_generic_to_shared(smem);
    const unsigned aRowOff = (unsigned)((wm * 64 + (lane & 15)) * 128);
    const unsigned bRowOff = (unsigned)((wn * 64 + ((lane & 16) >> 1) + (lane & 7)) * 128);
    int physA[4], physB[4];
    #pragma unroll
    for (int ks = 0; ks < 4; ks++){
        physA[ks] = ((2 * ks + (lane >> 4)) ^ (lane & 7)) * 16;
        physB[ks] = ((2 * ks + ((lane >> 3) & 1)) ^ (lane & 7)) * 16;
    }

    #define LOAD_TILE(KT, STG) do {                                            \
        float* A_s = smem + (STG) * GEMM_SMEM_STG;                             \
        float* B_s = A_s + GEMM_B_OFF;                                         \
        _Pragma("unroll")                                                      \
        for (int i = 0; i < 4; i++){                                           \
            int row  = lrow + i * 32;                                          \
            int phys = lkc ^ (row & 7);                                        \
            cp16(A_s + row * 32 + phys * 4,                                    \
                 (const char*)g_Ub + (size_t)(bm + row) * 2048 + (KT) * 128 + lkc * 16); \
        }                                                                      \
        _Pragma("unroll")                                                      \
        for (int i = 0; i < 8; i++){                                           \
            int row  = lrow + i * 32;                                          \
            int phys = lkc ^ (row & 7);                                        \
            cp16(B_s + row * 32 + phys * 4,                                    \
                 (const char*)g_Wb + (size_t)(bn + row) * 2048 + (KT) * 128 + lkc * 16); \
        }                                                                      \
        asm volatile("cp.async.commit_group;");                                \
    } while (0)

    LOAD_TILE(0, 0);

    for (int kt = 0; kt < 16; kt++){
        const int cur = kt & 1;
        if (kt < 15) LOAD_TILE(kt + 1, cur ^ 1);
        if (kt < 15) asm volatile("cp.async.wait_group 1;");
        else         asm volatile("cp.async.wait_group 0;");
        __syncthreads();

        unsigned aB = smemBase + cur * (GEMM_SMEM_STG * 4) + aRowOff;
        unsigned bB = smemBase + cur * (GEMM_SMEM_STG * 4) + GEMM_B_OFF * 4 + bRowOff;
        #pragma unroll
        for (int ks = 0; ks < 4; ks++){
            unsigned a[4][4], bb[4][4];
            #pragma unroll
            for (int mt = 0; mt < 4; mt++)
                ldsm4(a[mt], aB + mt * 16 * 128 + physA[ks]);
            #pragma unroll
            for (int tp = 0; tp < 4; tp++)
                ldsm4(bb[tp], bB + tp * 16 * 128 + physB[ks]);
            #pragma unroll
            for (int mt = 0; mt < 4; mt++)
                #pragma unroll
                for (int nt = 0; nt < 8; nt++)
                    mma_bf16(acc[mt][nt], a[mt],
                             bb[nt >> 1][(nt & 1) * 2], bb[nt >> 1][(nt & 1) * 2 + 1]);
        }
        __syncthreads();
    }

    const int rbase = bm + wm * 64 + (lane >> 2);
    const int gbase = bn + wn * 64 + 2 * (lane & 3);
    float bv[8][2];
    #pragma unroll
    for (int nt = 0; nt < 8; nt++){
        bv[nt][0] = __ldg(bias + gbase + nt * 8);
        bv[nt][1] = __ldg(bias + gbase + nt * 8 + 1);
    }
    #pragma unroll
    for (int mt = 0; mt < 4; mt++)
        #pragma unroll
        for (int nt = 0; nt < 8; nt++)
            #pragma unroll
            for (int rr = 0; rr < 2; rr++){
                const int m = rbase + mt * 16 + rr * 8;
                const int g0 = gbase + nt * 8;
                float v0 = acc[mt][nt][rr * 2]     + bv[nt][0];
                float v1 = acc[mt][nt][rr * 2 + 1] + bv[nt][1];
                float2 o;
                o.x = fminf(fmaxf(__expf(v0), DT_MIN_V), DT_MAX_V);
                o.y = fminf(fmaxf(__expf(v1), DT_MIN_V), DT_MAX_V);
                *(float2*)&g_dtv[(size_t)m * HDIM + g0] = o;
            }
}

// ---------------------------------------------------------------------------
// Step macros (register-only, fully inline).
// ---------------------------------------------------------------------------
#define FAST_STEP(uu) do {                                                     \
    const u64 _u2 = f2u((uu), (uu));                                           \
    _Pragma("unroll")                                                          \
    for (int _i = 0; _i < 8; _i++) x2[_i] = ffma2(x2[_i], am2[_i], _u2);       \
} while (0)

#define SLOW_STEP(dtv, uv) do {                                                \
    _Pragma("unroll")                                                          \
    for (int _i = 0; _i < 8; _i++){                                            \
        float2 _xv = u2f(x2[_i]);                                              \
        const float2 _av = u2f(am2[_i]);                                       \
        const float2 _lv = u2f(al2[_i]);                                       \
        {                                                                      \
            const float _ab = exp2f((dtv) * _lv.x);                            \
            _xv.x = fmaf(_xv.x, _ab, (_ab - 1.f) / (_av.x - 1.f) * (uv));      \
        }                                                                      \
        {                                                                      \
            const float _ab = exp2f((dtv) * _lv.y);                            \
            _xv.y = fmaf(_xv.y, _ab, (_ab - 1.f) / (_av.y - 1.f) * (uv));      \
        }                                                                      \
        x2[_i] = f2u(_xv.x, _xv.y);                                            \
    }                                                                          \
} while (0)

// ---------------------------------------------------------------------------
// Pass 1: per-(channel, group) reduce over 64 steps -> (Pg, Sg).
// u read from input, dt from g_dtv; al2 loaded lazily (rare path + epilogue).
// ---------------------------------------------------------------------------
__global__ __launch_bounds__(128) void scan_reduce_kernel(const float* __restrict__ u){
    const int tid = threadIdx.x;
    const int s = blockIdx.x * 128 + tid;
    const int g = blockIdx.y;
    const int b = s >> 10;
    const int h = s & 1023;

    u64 am2[8], x2[8];
    #pragma unroll
    for (int i = 0; i < 8; i++){
        am2[i] = g_am2T[i * HDIM + h];
        x2[i] = 0ull;
    }

    const size_t base = ((size_t)(b * LSEQ + g * GLEN)) * HDIM + h;
    const float* up = u + base;
    const float* dp = g_dtv + base;
    float dtsum = 0.f;

    #pragma unroll 1
    for (int bt = 0; bt < NB; bt++){
        float uu[16], dv[16];
        #pragma unroll
        for (int j = 0; j < 16; j++){
            uu[j] = __ldg(up + (size_t)(bt * 16 + j) * HDIM);
            dv[j] = __ldg(dp + (size_t)(bt * 16 + j) * HDIM);
        }
        bool fast = true;
        #pragma unroll
        for (int j = 0; j < 16; j++){ fast &= (dv[j] == DT_MAX_V); dtsum += dv[j]; }
        if (fast){
            #pragma unroll
            for (int j = 0; j < 16; j++) FAST_STEP(uu[j]);
        } else {
            u64 al2[8];
            #pragma unroll
            for (int i = 0; i < 8; i++) al2[i] = g_al2T[i * HDIM + h];
            #pragma unroll
            for (int j = 0; j < 16; j++){
                if (dv[j] == DT_MAX_V) FAST_STEP(uu[j]);
                else                   SLOW_STEP(dv[j], uu[j]);
            }
        }
    }

    float* Pp = g_Pg + (size_t)g * NST * NCH + s;
    float* Sp = g_Sg + (size_t)g * NST * NCH + s;
    #pragma unroll
    for (int i = 0; i < 8; i++){
        const float2 lv = u2f(g_al2T[i * HDIM + h]);
        const float2 xv = u2f(x2[i]);
        Pp[(size_t)(2 * i)     * NCH] = exp2f(lv.x * dtsum);
        Pp[(size_t)(2 * i + 1) * NCH] = exp2f(lv.y * dtsum);
        Sp[(size_t)(2 * i)     * NCH] = xv.x;
        Sp[(size_t)(2 * i + 1) * NCH] = xv.y;
    }
}

// ---------------------------------------------------------------------------
// Pass 2: fold 32 group aggregates -> group start states Xg.
// ---------------------------------------------------------------------------
#define STRIDE4 (NST*NCH/4)
__global__ void scan_stitch_kernel(){
    const int id = blockIdx.x * blockDim.x + threadIdx.x;  // 0..8191
    const float4* Pg4 = (const float4*)g_Pg;
    const float4* Sg4 = (const float4*)g_Sg;
    float4* Xg4 = (float4*)g_Xg;
    float4 x = make_float4(0.f, 0.f, 0.f, 0.f);
    #pragma unroll 1
    for (int r = 0; r < NGRP / 8; r++){
        float4 Pg[8], Sg[8];
        #pragma unroll
        for (int c = 0; c < 8; c++){
            Pg[c] = Pg4[(size_t)(r * 8 + c) * STRIDE4 + id];
            Sg[c] = Sg4[(size_t)(r * 8 + c) * STRIDE4 + id];
        }
        #pragma unroll
        for (int c = 0; c < 8; c++){
            Xg4[(size_t)(r * 8 + c) * STRIDE4 + id] = x;
            x.x = fmaf(Pg[c].x, x.x, Sg[c].x);
            x.y = fmaf(Pg[c].y, x.y, Sg[c].y);
            x.z = fmaf(Pg[c].z, x.z, Sg[c].z);
            x.w = fmaf(Pg[c].w, x.w, Sg[c].w);
        }
    }
}

// ---------------------------------------------------------------------------
// Pass 3: final scan + output. Thread = (channel, group); 64 steps from Xg.
// ---------------------------------------------------------------------------
__global__ __launch_bounds__(128) void scan_final_kernel(
        const float* __restrict__ Dp, const float* __restrict__ u,
        float* __restrict__ out){
    const int tid = threadIdx.x;
    const int s = blockIdx.x * 128 + tid;
    const int g = blockIdx.y;
    const int b = s >> 10;
    const int h = s & 1023;

    u64 am2[8], c2[8], x2[8];
    #pragma unroll
    for (int i = 0; i < 8; i++){
        am2[i] = g_am2T[i * HDIM + h];
        c2[i]  = g_c2T [i * HDIM + h];
    }
    const float Dh = __ldg(Dp + h);

    {
        const float* Xp = g_Xg + (size_t)g * NST * NCH + s;
        #pragma unroll
        for (int i = 0; i < 8; i++)
            x2[i] = f2u(Xp[(size_t)(2 * i) * NCH], Xp[(size_t)(2 * i + 1) * NCH]);
    }

    const size_t base = ((size_t)(b * LSEQ + g * GLEN)) * HDIM + h;
    const float* up = u + base;
    const float* dp = g_dtv + base;
    float* op = out + base;

    #define Y_EMIT(j, uv) do {                                                 \
        u64 ya = 0ull, yb = 0ull;                                              \
        _Pragma("unroll")                                                      \
        for (int _i = 0; _i < 4; _i++) ya = ffma2(c2[_i], x2[_i], ya);         \
        _Pragma("unroll")                                                      \
        for (int _i = 4; _i < 8; _i++) yb = ffma2(c2[_i], x2[_i], yb);         \
        const float2 _va = u2f(ya);                                            \
        const float2 _vb = u2f(yb);                                            \
        op[(size_t)(j) * HDIM] = fmaf(Dh, (uv), (_va.x + _va.y) + (_vb.x + _vb.y)); \
    } while (0)

    #pragma unroll 1
    for (int bt = 0; bt < NB; bt++){
        float uu[16], dv[16];
        #pragma unroll
        for (int j = 0; j < 16; j++){
            uu[j] = __ldg(up + (size_t)(bt * 16 + j) * HDIM);
            dv[j] = __ldg(dp + (size_t)(bt * 16 + j) * HDIM);
        }
        bool fast = true;
        #pragma unroll
        for (int j = 0; j < 16; j++) fast &= (dv[j] == DT_MAX_V);
        if (fast){
            #pragma unroll
            for (int j = 0; j < 16; j++){
                FAST_STEP(uu[j]);
                Y_EMIT(bt * 16 + j, uu[j]);
            }
        } else {
            u64 al2[8];
            #pragma unroll
            for (int i = 0; i < 8; i++) al2[i] = g_al2T[i * HDIM + h];
            #pragma unroll
            for (int j = 0; j < 16; j++){
                if (dv[j] == DT_MAX_V) FAST_STEP(uu[j]);
                else                   SLOW_STEP(dv[j], uu[j]);
                Y_EMIT(bt * 16 + j, uu[j]);
            }
        }
    }
    #undef Y_EMIT
}

// ---------------------------------------------------------------------------
extern "C" void kernel_launch(void* const* d_in, const int* in_sizes, int n_in,
                              void* d_out, int out_size){
    const float* u    = (const float*)d_in[0];
    const float* Alog = (const float*)d_in[1];
    const float* Bp   = (const float*)d_in[2];
    const float* Cp   = (const float*)d_in[3];
    const float* Dp   = (const float*)d_in[4];
    const float* Wdt  = (const float*)d_in[5];
    const float* bdt  = (const float*)d_in[6];
    float* out = (float*)d_out;

    cudaFuncSetAttribute(gemm_bf16_kernel,
                         cudaFuncAttributeMaxDynamicSharedMemorySize, 98304);

    convert_bf16_kernel<<<(MROWS * HDIM / 4 + HDIM * HDIM / 4) / 256, 256>>>(u, Wdt);
    precompute_kernel<<<HDIM / 128, 128>>>(Alog, Bp, Cp);

    dim3 ggrid(HDIM / 256, MROWS / 128);            // (4, 32) = 128 blocks
    gemm_bf16_kernel<<<ggrid, 256, 98304>>>(bdt);

    scan_reduce_kernel<<<dim3(NCH / 128, NGRP), 128>>>(u);
    scan_stitch_kernel<<<STRIDE4 / 256, 256>>>();
    scan_final_kernel<<<dim3(NCH / 128, NGRP), 128>>>(Dp, u, out);
}